// round 1
// baseline (speedup 1.0000x reference)
#include <cuda_runtime.h>
#include <math.h>

#define NN 50000
#define EE 600000
#define D_IN 16
#define DD 128
#define HH 4
#define DHH 32
#define LL 4
#define DFF 512
#define D_OUT 3

// ---------------- scratch (static device globals; no allocations) ----------------
__device__ float g_x[NN * DD];
__device__ float g_h[NN * DD];
__device__ float g_q[NN * DD];
__device__ float g_k[NN * DD];
__device__ float g_v[NN * DD];
__device__ float g_scores[EE * HH];
__device__ unsigned g_mkey[NN * HH];
__device__ float g_m[NN * HH];
__device__ float g_denom[NN * HH];
__device__ float g_msg[NN * DD];
__device__ float g_ffn[NN * DFF];

// ---------------- generic GEMM: C[n,MOUT] = act(A[n,MIN] @ W[MIN,MOUT] + bias) (+C) ----
// blockDim = 128 threads, ROWS=8 rows per block, each thread owns MOUT/128 columns.
template <int MIN, int MOUT, bool RELU, bool ADD>
__global__ void gemm_kernel(const float* __restrict__ A, const float* __restrict__ W,
                            const float* __restrict__ bias, float* __restrict__ C, int n) {
    constexpr int ROWS = 8;
    constexpr int CPT = MOUT / 128;
    __shared__ float sA[ROWS][MIN];
    int row0 = blockIdx.x * ROWS;

    for (int i = threadIdx.x; i < ROWS * MIN; i += 128) {
        int r = i / MIN, k = i % MIN;
        int row = row0 + r;
        sA[r][k] = (row < n) ? A[row * MIN + k] : 0.f;
    }
    __syncthreads();

    float acc[ROWS][CPT];
#pragma unroll
    for (int r = 0; r < ROWS; r++)
#pragma unroll
        for (int c = 0; c < CPT; c++) acc[r][c] = 0.f;

    for (int k = 0; k < MIN; ++k) {
        float w[CPT];
#pragma unroll
        for (int c = 0; c < CPT; c++) w[c] = W[k * MOUT + threadIdx.x + c * 128];
#pragma unroll
        for (int r = 0; r < ROWS; r++) {
            float a = sA[r][k];
#pragma unroll
            for (int c = 0; c < CPT; c++) acc[r][c] += a * w[c];
        }
    }

#pragma unroll
    for (int r = 0; r < ROWS; r++) {
        int row = row0 + r;
        if (row >= n) break;
#pragma unroll
        for (int c = 0; c < CPT; c++) {
            int col = threadIdx.x + c * 128;
            float val = acc[r][c];
            if (bias) val += bias[col];
            if (RELU) val = fmaxf(val, 0.f);
            if (ADD) val += C[row * MOUT + col];
            C[row * MOUT + col] = val;
        }
    }
}

// ---------------- LayerNorm: warp per row ----------------
__global__ void ln_kernel(const float* __restrict__ x, const float* __restrict__ s,
                          const float* __restrict__ b, float* __restrict__ out, int n) {
    int row = blockIdx.x * 8 + (threadIdx.x >> 5);
    if (row >= n) return;
    int lane = threadIdx.x & 31;
    float4 v = *(const float4*)(x + row * DD + lane * 4);
    float sum = v.x + v.y + v.z + v.w;
    float sq = v.x * v.x + v.y * v.y + v.z * v.z + v.w * v.w;
#pragma unroll
    for (int off = 16; off; off >>= 1) {
        sum += __shfl_xor_sync(0xffffffffu, sum, off);
        sq += __shfl_xor_sync(0xffffffffu, sq, off);
    }
    float mu = sum * (1.f / 128.f);
    float var = sq * (1.f / 128.f) - mu * mu;
    float rstd = rsqrtf(var + 1e-5f);
    float4 sv = *(const float4*)(s + lane * 4);
    float4 bv = *(const float4*)(b + lane * 4);
    float4 o;
    o.x = (v.x - mu) * rstd * sv.x + bv.x;
    o.y = (v.y - mu) * rstd * sv.y + bv.y;
    o.z = (v.z - mu) * rstd * sv.z + bv.z;
    o.w = (v.w - mu) * rstd * sv.w + bv.w;
    *(float4*)(out + row * DD + lane * 4) = o;
}

// ---------------- clear per-layer accumulators ----------------
__global__ void clear_kernel() {
    int i = blockIdx.x * blockDim.x + threadIdx.x;
    if (i < NN * HH) {
        g_mkey[i] = 0u;
        g_denom[i] = 0.f;
    }
    if (i < NN * DD / 4) ((float4*)g_msg)[i] = make_float4(0.f, 0.f, 0.f, 0.f);
}

// ---------------- edge scores: warp per edge ----------------
__global__ void scores_kernel(const int* __restrict__ senders, const int* __restrict__ receivers) {
    int e = blockIdx.x * 4 + (threadIdx.x >> 5);
    if (e >= EE) return;
    int lane = threadIdx.x & 31;
    int snd = senders[e], rcv = receivers[e];
    float4 qv = *(const float4*)(g_q + (size_t)rcv * DD + lane * 4);
    float4 kv = *(const float4*)(g_k + (size_t)snd * DD + lane * 4);
    float p = qv.x * kv.x + qv.y * kv.y + qv.z * kv.z + qv.w * kv.w;
#pragma unroll
    for (int off = 4; off; off >>= 1) p += __shfl_down_sync(0xffffffffu, p, off);
    if ((lane & 7) == 0) g_scores[e * HH + (lane >> 3)] = p * 0.17677669529663687f; // 1/sqrt(32)
}

// ---------------- segment max via ordered-uint atomicMax ----------------
__device__ __forceinline__ unsigned f2key(float f) {
    unsigned u = __float_as_uint(f);
    return (u & 0x80000000u) ? ~u : (u | 0x80000000u);
}

__global__ void segmax_kernel(const int* __restrict__ receivers) {
    int i = blockIdx.x * blockDim.x + threadIdx.x;
    if (i >= EE * HH) return;
    int e = i >> 2;
    int h = i & 3;
    int rcv = receivers[e];
    atomicMax(&g_mkey[rcv * HH + h], f2key(g_scores[e * HH + h]));
}

__global__ void decode_m_kernel() {
    int i = blockIdx.x * blockDim.x + threadIdx.x;
    if (i >= NN * HH) return;
    unsigned key = g_mkey[i];
    float m = 0.f;
    if (key != 0u) {
        unsigned u = (key & 0x80000000u) ? (key ^ 0x80000000u) : ~key;
        m = __uint_as_float(u);
    }
    g_m[i] = m;
}

// ---------------- edge accumulate: warp per edge ----------------
__global__ void accum_kernel(const int* __restrict__ senders, const int* __restrict__ receivers) {
    int e = blockIdx.x * 4 + (threadIdx.x >> 5);
    if (e >= EE) return;
    int lane = threadIdx.x & 31;
    int snd = senders[e], rcv = receivers[e];
    float a_l = 0.f;
    if (lane < HH) {
        float sc = g_scores[e * HH + lane];
        a_l = expf(sc - g_m[rcv * HH + lane]);
        atomicAdd(&g_denom[rcv * HH + lane], a_l);
    }
    int head = lane >> 3;
    float a = __shfl_sync(0xffffffffu, a_l, head);
    float4 vv = *(const float4*)(g_v + (size_t)snd * DD + lane * 4);
    float* dst = g_msg + (size_t)rcv * DD + lane * 4;
    atomicAdd(dst + 0, a * vv.x);
    atomicAdd(dst + 1, a * vv.y);
    atomicAdd(dst + 2, a * vv.z);
    atomicAdd(dst + 3, a * vv.w);
}

// ---------------- msg / denom -> h ----------------
__global__ void finalize_kernel() {
    int i = blockIdx.x * blockDim.x + threadIdx.x;
    if (i >= NN * DD) return;
    int row = i >> 7;      // /128
    int j = i & 127;
    int head = j >> 5;
    g_h[i] = g_msg[i] / (g_denom[row * HH + head] + 1e-9f);
}

// ---------------- decoder: warp per row ----------------
__global__ void decode_kernel(const float* __restrict__ x, const float* __restrict__ w1,
                              const float* __restrict__ b1, const float* __restrict__ w2,
                              const float* __restrict__ b2, float* __restrict__ out, int n) {
    int row = blockIdx.x * 4 + (threadIdx.x >> 5);
    if (row >= n) return;
    int lane = threadIdx.x & 31;
    float4 xr = *(const float4*)(x + row * DD + lane * 4);
    float t[3];
#pragma unroll
    for (int o = 0; o < 3; o++) {
        float p = xr.x * w1[(lane * 4 + 0) * 3 + o] + xr.y * w1[(lane * 4 + 1) * 3 + o] +
                  xr.z * w1[(lane * 4 + 2) * 3 + o] + xr.w * w1[(lane * 4 + 3) * 3 + o];
#pragma unroll
        for (int off = 16; off; off >>= 1) p += __shfl_down_sync(0xffffffffu, p, off);
        t[o] = p;
    }
    if (lane == 0) {
        float r0 = fmaxf(t[0] + b1[0], 0.f);
        float r1 = fmaxf(t[1] + b1[1], 0.f);
        float r2 = fmaxf(t[2] + b1[2], 0.f);
#pragma unroll
        for (int o2 = 0; o2 < 3; o2++)
            out[row * 3 + o2] = r0 * w2[0 * 3 + o2] + r1 * w2[1 * 3 + o2] + r2 * w2[2 * 3 + o2] + b2[o2];
    }
}

// ---------------- host orchestration ----------------
extern "C" void kernel_launch(void* const* d_in, const int* in_sizes, int n_in,
                              void* d_out, int out_size) {
    const float* features = (const float*)d_in[0];
    const int* senders = (const int*)d_in[1];
    const int* receivers = (const int*)d_in[2];
    const float* enc_w1 = (const float*)d_in[3];
    const float* enc_b1 = (const float*)d_in[4];
    const float* enc_w2 = (const float*)d_in[5];
    const float* enc_b2 = (const float*)d_in[6];
    const float* wq = (const float*)d_in[7];
    const float* wk = (const float*)d_in[8];
    const float* wv = (const float*)d_in[9];
    const float* wo = (const float*)d_in[10];
    const float* ln1_s = (const float*)d_in[11];
    const float* ln1_b = (const float*)d_in[12];
    const float* ffn_w1 = (const float*)d_in[13];
    const float* ffn_b1 = (const float*)d_in[14];
    const float* ffn_w2 = (const float*)d_in[15];
    const float* ffn_b2 = (const float*)d_in[16];
    const float* ln2_s = (const float*)d_in[17];
    const float* ln2_b = (const float*)d_in[18];
    const float* dec_w1 = (const float*)d_in[19];
    const float* dec_b1 = (const float*)d_in[20];
    const float* dec_w2 = (const float*)d_in[21];
    const float* dec_b2 = (const float*)d_in[22];
    float* out = (float*)d_out;

    float* x;  cudaGetSymbolAddress((void**)&x, g_x);
    float* h;  cudaGetSymbolAddress((void**)&h, g_h);
    float* q;  cudaGetSymbolAddress((void**)&q, g_q);
    float* k;  cudaGetSymbolAddress((void**)&k, g_k);
    float* v;  cudaGetSymbolAddress((void**)&v, g_v);
    float* ffn; cudaGetSymbolAddress((void**)&ffn, g_ffn);

    const int GEMM_GRID = (NN + 7) / 8;  // 6250

    // encode
    gemm_kernel<D_IN, DD, true, false><<<GEMM_GRID, 128>>>(features, enc_w1, enc_b1, h, NN);
    gemm_kernel<DD, DD, false, false><<<GEMM_GRID, 128>>>(h, enc_w2, enc_b2, x, NN);

    for (int l = 0; l < LL; l++) {
        const float* wq_l = wq + (size_t)l * DD * DD;
        const float* wk_l = wk + (size_t)l * DD * DD;
        const float* wv_l = wv + (size_t)l * DD * DD;
        const float* wo_l = wo + (size_t)l * DD * DD;

        // attention sub-block
        ln_kernel<<<(NN + 7) / 8, 256>>>(x, ln1_s + l * DD, ln1_b + l * DD, h, NN);
        gemm_kernel<DD, DD, false, false><<<GEMM_GRID, 128>>>(h, wq_l, nullptr, q, NN);
        gemm_kernel<DD, DD, false, false><<<GEMM_GRID, 128>>>(h, wk_l, nullptr, k, NN);
        gemm_kernel<DD, DD, false, false><<<GEMM_GRID, 128>>>(h, wv_l, nullptr, v, NN);

        clear_kernel<<<(NN * DD / 4 + 255) / 256, 256>>>();
        scores_kernel<<<(EE + 3) / 4, 128>>>(senders, receivers);
        segmax_kernel<<<(EE * HH + 255) / 256, 256>>>(receivers);
        decode_m_kernel<<<(NN * HH + 255) / 256, 256>>>();
        accum_kernel<<<(EE + 3) / 4, 128>>>(senders, receivers);
        finalize_kernel<<<(NN * DD + 255) / 256, 256>>>();
        gemm_kernel<DD, DD, false, true><<<GEMM_GRID, 128>>>(h, wo_l, nullptr, x, NN);

        // FFN sub-block
        ln_kernel<<<(NN + 7) / 8, 256>>>(x, ln2_s + l * DD, ln2_b + l * DD, h, NN);
        gemm_kernel<DD, DFF, true, false><<<GEMM_GRID, 128>>>(h, ffn_w1 + (size_t)l * DD * DFF,
                                                              ffn_b1 + l * DFF, ffn, NN);
        gemm_kernel<DFF, DD, false, true><<<GEMM_GRID, 128>>>(ffn, ffn_w2 + (size_t)l * DFF * DD,
                                                              ffn_b2 + l * DD, x, NN);
    }

    // decode
    decode_kernel<<<(NN + 3) / 4, 128>>>(x, dec_w1, dec_b1, dec_w2, dec_b2, out, NN);
}

// round 2
// speedup vs baseline: 1.6300x; 1.6300x over previous
#include <cuda_runtime.h>
#include <math.h>

#define NN 50000
#define EE 600000
#define D_IN 16
#define DD 128
#define HH 4
#define DHH 32
#define LL 4
#define DFF 512
#define D_OUT 3

// ---------------- scratch (static device globals; no allocations) ----------------
__device__ float g_x[NN * DD];
__device__ float g_h[NN * DD];
__device__ float g_q[NN * DD];
__device__ float g_k[NN * DD];
__device__ float g_v[NN * DD];
__device__ float g_ffn[NN * DFF];
__device__ int g_cnt[NN];
__device__ int g_cur[NN];
__device__ int g_rowptr[NN + 1];
__device__ int g_csr_snd[EE];

// ---------------- register-blocked GEMM ----------------
// C[n,MOUT] = act(A[n,K] @ W[K,MOUT] + bias) (+C if ADD)
// 64x128 tile, BK=16, 256 threads, 8x4 micro-tile per thread.
template <int K, int MOUT, bool RELU, bool ADD>
__global__ void __launch_bounds__(256) gemm_kernel(const float* __restrict__ A,
                                                   const float* __restrict__ W,
                                                   const float* __restrict__ bias,
                                                   float* __restrict__ C, int n) {
    constexpr int BM = 64, BN = 128, BK = 16;
    constexpr int TM = 8, TN = 4;
    __shared__ float As[BK][BM + 4];
    __shared__ float Ws[BK][BN];

    int row0 = blockIdx.x * BM;
    int col0 = blockIdx.y * BN;
    int tid = threadIdx.x;
    int tx = tid & 31;   // 32 col-groups of TN=4
    int ty = tid >> 5;   // 8 row-groups of TM=8

    float acc[TM][TN];
#pragma unroll
    for (int i = 0; i < TM; i++)
#pragma unroll
        for (int j = 0; j < TN; j++) acc[i][j] = 0.f;

    int a_row = tid >> 2;          // 0..63
    int a_kq = (tid & 3) * 4;      // 0,4,8,12

    for (int k0 = 0; k0 < K; k0 += BK) {
        // stage A tile (transposed into smem)
        float4 av = make_float4(0.f, 0.f, 0.f, 0.f);
        int grow = row0 + a_row;
        if (grow < n) av = *(const float4*)(A + (size_t)grow * K + k0 + a_kq);
        As[a_kq + 0][a_row] = av.x;
        As[a_kq + 1][a_row] = av.y;
        As[a_kq + 2][a_row] = av.z;
        As[a_kq + 3][a_row] = av.w;
        // stage W tile: 16x128 = 2 float4 per thread
#pragma unroll
        for (int i = 0; i < 2; i++) {
            int lin = tid + i * 256;
            int wk = lin >> 5;
            int wc = (lin & 31) * 4;
            *(float4*)&Ws[wk][wc] = *(const float4*)(W + (size_t)(k0 + wk) * MOUT + col0 + wc);
        }
        __syncthreads();

#pragma unroll
        for (int kk = 0; kk < BK; kk++) {
            float a[TM], w[TN];
            *(float4*)&a[0] = *(float4*)&As[kk][ty * TM];
            *(float4*)&a[4] = *(float4*)&As[kk][ty * TM + 4];
            *(float4*)&w[0] = *(float4*)&Ws[kk][tx * TN];
#pragma unroll
            for (int i = 0; i < TM; i++)
#pragma unroll
                for (int j = 0; j < TN; j++) acc[i][j] += a[i] * w[j];
        }
        __syncthreads();
    }

    float bv[TN] = {0.f, 0.f, 0.f, 0.f};
    if (bias) {
#pragma unroll
        for (int j = 0; j < TN; j++) bv[j] = bias[col0 + tx * TN + j];
    }
#pragma unroll
    for (int i = 0; i < TM; i++) {
        int row = row0 + ty * TM + i;
        if (row < n) {
            float* cp = C + (size_t)row * MOUT + col0 + tx * TN;
            float4 o;
            o.x = acc[i][0] + bv[0];
            o.y = acc[i][1] + bv[1];
            o.z = acc[i][2] + bv[2];
            o.w = acc[i][3] + bv[3];
            if (RELU) {
                o.x = fmaxf(o.x, 0.f); o.y = fmaxf(o.y, 0.f);
                o.z = fmaxf(o.z, 0.f); o.w = fmaxf(o.w, 0.f);
            }
            if (ADD) {
                float4 c = *(const float4*)cp;
                o.x += c.x; o.y += c.y; o.z += c.z; o.w += c.w;
            }
            *(float4*)cp = o;
        }
    }
}

// ---------------- LayerNorm: warp per row ----------------
__global__ void ln_kernel(const float* __restrict__ x, const float* __restrict__ s,
                          const float* __restrict__ b, float* __restrict__ out, int n) {
    int row = blockIdx.x * 8 + (threadIdx.x >> 5);
    if (row >= n) return;
    int lane = threadIdx.x & 31;
    float4 v = *(const float4*)(x + (size_t)row * DD + lane * 4);
    float sum = v.x + v.y + v.z + v.w;
    float sq = v.x * v.x + v.y * v.y + v.z * v.z + v.w * v.w;
#pragma unroll
    for (int off = 16; off; off >>= 1) {
        sum += __shfl_xor_sync(0xffffffffu, sum, off);
        sq += __shfl_xor_sync(0xffffffffu, sq, off);
    }
    float mu = sum * (1.f / 128.f);
    float var = sq * (1.f / 128.f) - mu * mu;
    float rstd = rsqrtf(var + 1e-5f);
    float4 sv = *(const float4*)(s + lane * 4);
    float4 bv = *(const float4*)(b + lane * 4);
    float4 o;
    o.x = (v.x - mu) * rstd * sv.x + bv.x;
    o.y = (v.y - mu) * rstd * sv.y + bv.y;
    o.z = (v.z - mu) * rstd * sv.z + bv.z;
    o.w = (v.w - mu) * rstd * sv.w + bv.w;
    *(float4*)(out + (size_t)row * DD + lane * 4) = o;
}

// ---------------- CSR build (by receiver) ----------------
__global__ void zero_cnt_kernel() {
    int i = blockIdx.x * blockDim.x + threadIdx.x;
    if (i < NN) g_cnt[i] = 0;
}

__global__ void hist_kernel(const int* __restrict__ receivers) {
    int e = blockIdx.x * blockDim.x + threadIdx.x;
    if (e < EE) atomicAdd(&g_cnt[receivers[e]], 1);
}

// single-block scan: g_rowptr (exclusive prefix) and g_cur (scatter cursors)
__global__ void scan_kernel() {
    __shared__ int warp_sums[32];
    __shared__ int s_carry;
    int lane = threadIdx.x & 31;
    int wid = threadIdx.x >> 5;
    if (threadIdx.x == 0) s_carry = 0;
    __syncthreads();
    for (int base = 0; base < NN; base += 1024) {
        int i = base + threadIdx.x;
        int v = (i < NN) ? g_cnt[i] : 0;
        int incl = v;
#pragma unroll
        for (int off = 1; off < 32; off <<= 1) {
            int t = __shfl_up_sync(0xffffffffu, incl, off);
            if (lane >= off) incl += t;
        }
        if (lane == 31) warp_sums[wid] = incl;
        __syncthreads();
        if (wid == 0) {
            int ws = warp_sums[lane];
            int wincl = ws;
#pragma unroll
            for (int off = 1; off < 32; off <<= 1) {
                int t = __shfl_up_sync(0xffffffffu, wincl, off);
                if (lane >= off) wincl += t;
            }
            warp_sums[lane] = wincl - ws;  // exclusive warp offset
        }
        __syncthreads();
        int total_incl = s_carry + warp_sums[wid] + incl;
        if (i < NN) {
            g_rowptr[i + 1] = total_incl;
            g_cur[i] = total_incl - v;
        }
        __syncthreads();
        if (threadIdx.x == 1023) s_carry = total_incl;
        __syncthreads();
    }
    if (threadIdx.x == 0) g_rowptr[0] = 0;
}

__global__ void scatter_kernel(const int* __restrict__ senders,
                               const int* __restrict__ receivers) {
    int e = blockIdx.x * blockDim.x + threadIdx.x;
    if (e >= EE) return;
    int pos = atomicAdd(&g_cur[receivers[e]], 1);
    g_csr_snd[pos] = senders[e];
}

// ---------------- fused sparse attention: warp per (node, head) ----------------
__global__ void attn_kernel() {
    int w = (blockIdx.x * blockDim.x + threadIdx.x) >> 5;
    if (w >= NN * HH) return;
    int lane = threadIdx.x & 31;
    int node = w >> 2;
    int head = w & 3;
    int off = head * DHH + lane;

    float qv = g_q[(size_t)node * DD + off];
    int beg = g_rowptr[node], end = g_rowptr[node + 1];

    float m = -INFINITY, den = 0.f, acc = 0.f;
    for (int j = beg; j < end; j++) {
        int snd = g_csr_snd[j];
        float kv = g_k[(size_t)snd * DD + off];
        float d = qv * kv;
#pragma unroll
        for (int o = 16; o; o >>= 1) d += __shfl_xor_sync(0xffffffffu, d, o);
        float s = d * 0.17677669529663687f;  // 1/sqrt(32)
        float nm = fmaxf(m, s);
        float alpha = __expf(m - nm);
        float a = __expf(s - nm);
        den = den * alpha + a;
        acc = acc * alpha + a * g_v[(size_t)snd * DD + off];
        m = nm;
    }
    g_h[(size_t)node * DD + off] = acc / (den + 1e-9f);
}

// ---------------- decoder: warp per row ----------------
__global__ void decode_kernel(const float* __restrict__ x, const float* __restrict__ w1,
                              const float* __restrict__ b1, const float* __restrict__ w2,
                              const float* __restrict__ b2, float* __restrict__ out, int n) {
    int row = blockIdx.x * 4 + (threadIdx.x >> 5);
    if (row >= n) return;
    int lane = threadIdx.x & 31;
    float4 xr = *(const float4*)(x + (size_t)row * DD + lane * 4);
    float t[3];
#pragma unroll
    for (int o = 0; o < 3; o++) {
        float p = xr.x * w1[(lane * 4 + 0) * 3 + o] + xr.y * w1[(lane * 4 + 1) * 3 + o] +
                  xr.z * w1[(lane * 4 + 2) * 3 + o] + xr.w * w1[(lane * 4 + 3) * 3 + o];
#pragma unroll
        for (int off = 16; off; off >>= 1) p += __shfl_down_sync(0xffffffffu, p, off);
        t[o] = p;
    }
    if (lane == 0) {
        float r0 = fmaxf(t[0] + b1[0], 0.f);
        float r1 = fmaxf(t[1] + b1[1], 0.f);
        float r2 = fmaxf(t[2] + b1[2], 0.f);
#pragma unroll
        for (int o2 = 0; o2 < 3; o2++)
            out[row * 3 + o2] = r0 * w2[0 * 3 + o2] + r1 * w2[1 * 3 + o2] + r2 * w2[2 * 3 + o2] + b2[o2];
    }
}

// ---------------- host orchestration ----------------
extern "C" void kernel_launch(void* const* d_in, const int* in_sizes, int n_in,
                              void* d_out, int out_size) {
    const float* features = (const float*)d_in[0];
    const int* senders = (const int*)d_in[1];
    const int* receivers = (const int*)d_in[2];
    const float* enc_w1 = (const float*)d_in[3];
    const float* enc_b1 = (const float*)d_in[4];
    const float* enc_w2 = (const float*)d_in[5];
    const float* enc_b2 = (const float*)d_in[6];
    const float* wq = (const float*)d_in[7];
    const float* wk = (const float*)d_in[8];
    const float* wv = (const float*)d_in[9];
    const float* wo = (const float*)d_in[10];
    const float* ln1_s = (const float*)d_in[11];
    const float* ln1_b = (const float*)d_in[12];
    const float* ffn_w1 = (const float*)d_in[13];
    const float* ffn_b1 = (const float*)d_in[14];
    const float* ffn_w2 = (const float*)d_in[15];
    const float* ffn_b2 = (const float*)d_in[16];
    const float* ln2_s = (const float*)d_in[17];
    const float* ln2_b = (const float*)d_in[18];
    const float* dec_w1 = (const float*)d_in[19];
    const float* dec_b1 = (const float*)d_in[20];
    const float* dec_w2 = (const float*)d_in[21];
    const float* dec_b2 = (const float*)d_in[22];
    float* out = (float*)d_out;

    float* x;   cudaGetSymbolAddress((void**)&x, g_x);
    float* h;   cudaGetSymbolAddress((void**)&h, g_h);
    float* q;   cudaGetSymbolAddress((void**)&q, g_q);
    float* k;   cudaGetSymbolAddress((void**)&k, g_k);
    float* v;   cudaGetSymbolAddress((void**)&v, g_v);
    float* ffn; cudaGetSymbolAddress((void**)&ffn, g_ffn);

    const int MB = (NN + 63) / 64;  // 782 row tiles
    dim3 g128(MB, 1), g512(MB, 4);

    // CSR build (receiver-sorted edges), once per call
    zero_cnt_kernel<<<(NN + 255) / 256, 256>>>();
    hist_kernel<<<(EE + 255) / 256, 256>>>(receivers);
    scan_kernel<<<1, 1024>>>();
    scatter_kernel<<<(EE + 255) / 256, 256>>>(senders, receivers);

    // encode
    gemm_kernel<D_IN, DD, true, false><<<g128, 256>>>(features, enc_w1, enc_b1, h, NN);
    gemm_kernel<DD, DD, false, false><<<g128, 256>>>(h, enc_w2, enc_b2, x, NN);

    for (int l = 0; l < LL; l++) {
        const float* wq_l = wq + (size_t)l * DD * DD;
        const float* wk_l = wk + (size_t)l * DD * DD;
        const float* wv_l = wv + (size_t)l * DD * DD;
        const float* wo_l = wo + (size_t)l * DD * DD;

        // attention sub-block
        ln_kernel<<<(NN + 7) / 8, 256>>>(x, ln1_s + l * DD, ln1_b + l * DD, h, NN);
        gemm_kernel<DD, DD, false, false><<<g128, 256>>>(h, wq_l, nullptr, q, NN);
        gemm_kernel<DD, DD, false, false><<<g128, 256>>>(h, wk_l, nullptr, k, NN);
        gemm_kernel<DD, DD, false, false><<<g128, 256>>>(h, wv_l, nullptr, v, NN);
        attn_kernel<<<(NN * HH + 7) / 8, 256>>>();
        gemm_kernel<DD, DD, false, true><<<g128, 256>>>(h, wo_l, nullptr, x, NN);

        // FFN sub-block
        ln_kernel<<<(NN + 7) / 8, 256>>>(x, ln2_s + l * DD, ln2_b + l * DD, h, NN);
        gemm_kernel<DD, DFF, true, false><<<g512, 256>>>(h, ffn_w1 + (size_t)l * DD * DFF,
                                                         ffn_b1 + l * DFF, ffn, NN);
        gemm_kernel<DFF, DD, false, true><<<g128, 256>>>(ffn, ffn_w2 + (size_t)l * DFF * DD,
                                                         ffn_b2 + l * DD, x, NN);
    }

    // decode
    decode_kernel<<<(NN + 3) / 4, 128>>>(x, dec_w1, dec_b1, dec_w2, dec_b2, out, NN);
}

// round 4
// speedup vs baseline: 2.2777x; 1.3973x over previous
#include <cuda_runtime.h>
#include <cuda_bf16.h>
#include <cstdint>
#include <math.h>

#define NN 50000
#define EE 600000
#define D_IN 16
#define DD 128
#define HH 4
#define DHH 32
#define LL 4
#define DFF 512
#define D_OUT 3

// ---------------- scratch ----------------
__device__ float g_x[NN * DD];
__device__ float g_h[NN * DD];
__device__ float g_q[NN * DD];
__device__ float g_k[NN * DD];
__device__ float g_v[NN * DD];
__device__ float g_ffn[NN * DFF];
__device__ int g_cnt[NN];
__device__ int g_cur[NN];
__device__ int g_rowptr[NN + 1];
__device__ int g_csr_snd[EE];

// ---------------- helpers ----------------
__device__ __forceinline__ void hmma_bf16(float* c, const uint32_t* a, uint32_t b0, uint32_t b1) {
    asm volatile(
        "mma.sync.aligned.m16n8k16.row.col.f32.bf16.bf16.f32 "
        "{%0,%1,%2,%3}, {%4,%5,%6,%7}, {%8,%9}, {%0,%1,%2,%3};"
        : "+f"(c[0]), "+f"(c[1]), "+f"(c[2]), "+f"(c[3])
        : "r"(a[0]), "r"(a[1]), "r"(a[2]), "r"(a[3]), "r"(b0), "r"(b1));
}
__device__ __forceinline__ void split2(float x, float y, uint32_t& hi, uint32_t& lo) {
    __nv_bfloat16 hx = __float2bfloat16(x);
    __nv_bfloat16 hy = __float2bfloat16(y);
    __nv_bfloat16 lx = __float2bfloat16(x - __bfloat162float(hx));
    __nv_bfloat16 ly = __float2bfloat16(y - __bfloat162float(hy));
    __nv_bfloat162 hp = __halves2bfloat162(hx, hy);
    __nv_bfloat162 lp = __halves2bfloat162(lx, ly);
    hi = *(uint32_t*)&hp;
    lo = *(uint32_t*)&lp;
}

// ---------------- HMMA bf16x3 GEMM ----------------
// C[n,MOUT] = act(A[n,K] @ W[K,MOUT] + bias) (+C if ADD)
// Block tile 128x128, BK=32, 256 threads = 8 warps (4 m x 2 n), warp tile 32x64.
template <int K, int MOUT, bool RELU, bool ADD>
__global__ void __launch_bounds__(256) gemm_mma(const float* __restrict__ A,
                                                const float* __restrict__ W,
                                                const float* __restrict__ bias,
                                                float* __restrict__ C, int n) {
    constexpr int STR = 20;  // smem row stride in 32-bit words (16 used + pad) -> conflict-free frags
    __shared__ uint32_t sAhi[128][STR];
    __shared__ uint32_t sAlo[128][STR];
    __shared__ uint32_t sBhi[128][STR];
    __shared__ uint32_t sBlo[128][STR];

    int tid = threadIdx.x;
    int l = tid & 31;
    int wm = (tid >> 5) & 3;   // warp m index (0..3)
    int wn = tid >> 7;         // warp n index (0..1)
    int row0 = blockIdx.x * 128, col0 = blockIdx.y * 128;

    float acc[2][8][4];
#pragma unroll
    for (int a = 0; a < 2; a++)
#pragma unroll
        for (int b = 0; b < 8; b++)
#pragma unroll
            for (int c = 0; c < 4; c++) acc[a][b][c] = 0.f;

    const int ar = tid >> 1;        // A staging row 0..127
    const int akh = tid & 1;        // A staging k-half
    const int bn = tid & 127;       // B staging column
    const int bkh = tid >> 7;       // B staging k-half

    for (int k0 = 0; k0 < K; k0 += 32) {
        __syncthreads();
        // ---- stage A: rows row0..row0+127, k k0..k0+31, fp32 -> hi/lo bf16 pairs ----
        {
            int grow = row0 + ar;
            const float4* ap = (const float4*)(A + (size_t)grow * K + k0 + akh * 16);
            float4 f[4];
#pragma unroll
            for (int q = 0; q < 4; q++)
                f[q] = (grow < n) ? ap[q] : make_float4(0.f, 0.f, 0.f, 0.f);
#pragma unroll
            for (int q = 0; q < 4; q++) {
                uint32_t h0, l0, h1, l1;
                split2(f[q].x, f[q].y, h0, l0);
                split2(f[q].z, f[q].w, h1, l1);
                sAhi[ar][akh * 8 + 2 * q] = h0;
                sAhi[ar][akh * 8 + 2 * q + 1] = h1;
                sAlo[ar][akh * 8 + 2 * q] = l0;
                sAlo[ar][akh * 8 + 2 * q + 1] = l1;
            }
        }
        // ---- stage B (W transposed): sB[n][k] = W[k0+k][col0+n] ----
        {
            const float* wp = W + (size_t)(k0 + bkh * 16) * MOUT + col0 + bn;
#pragma unroll
            for (int p = 0; p < 8; p++) {
                float w0 = wp[(size_t)(2 * p) * MOUT];
                float w1 = wp[(size_t)(2 * p + 1) * MOUT];
                uint32_t h, lo;
                split2(w0, w1, h, lo);
                sBhi[bn][bkh * 8 + p] = h;
                sBlo[bn][bkh * 8 + p] = lo;
            }
        }
        __syncthreads();

        // ---- compute: 2 k16 steps ----
#pragma unroll
        for (int ks = 0; ks < 2; ks++) {
            int w = 8 * ks + (l & 3);
            uint32_t ah[2][4], al[2][4];
#pragma unroll
            for (int tm = 0; tm < 2; tm++) {
                int r0 = wm * 32 + tm * 16 + (l >> 2);
                ah[tm][0] = sAhi[r0][w];
                ah[tm][1] = sAhi[r0 + 8][w];
                ah[tm][2] = sAhi[r0][w + 4];
                ah[tm][3] = sAhi[r0 + 8][w + 4];
                al[tm][0] = sAlo[r0][w];
                al[tm][1] = sAlo[r0 + 8][w];
                al[tm][2] = sAlo[r0][w + 4];
                al[tm][3] = sAlo[r0 + 8][w + 4];
            }
#pragma unroll
            for (int tn = 0; tn < 8; tn++) {
                int nn = wn * 64 + tn * 8 + (l >> 2);
                uint32_t bh0 = sBhi[nn][w], bh1 = sBhi[nn][w + 4];
                uint32_t bl0 = sBlo[nn][w], bl1 = sBlo[nn][w + 4];
#pragma unroll
                for (int tm = 0; tm < 2; tm++) {
                    hmma_bf16(acc[tm][tn], ah[tm], bh0, bh1);
                    hmma_bf16(acc[tm][tn], ah[tm], bl0, bl1);
                    hmma_bf16(acc[tm][tn], al[tm], bh0, bh1);
                }
            }
        }
    }

    // ---- epilogue ----
#pragma unroll
    for (int tm = 0; tm < 2; tm++) {
#pragma unroll
        for (int tn = 0; tn < 8; tn++) {
            int row = row0 + wm * 32 + tm * 16 + (l >> 2);
            int col = col0 + wn * 64 + tn * 8 + (l & 3) * 2;
            float b0 = 0.f, b1 = 0.f;
            if (bias) { b0 = bias[col]; b1 = bias[col + 1]; }
#pragma unroll
            for (int half = 0; half < 2; half++) {
                int r = row + half * 8;
                if (r < n) {
                    float v0 = acc[tm][tn][half * 2 + 0] + b0;
                    float v1 = acc[tm][tn][half * 2 + 1] + b1;
                    if (RELU) { v0 = fmaxf(v0, 0.f); v1 = fmaxf(v1, 0.f); }
                    float2* cp = (float2*)(C + (size_t)r * MOUT + col);
                    if (ADD) {
                        float2 old = *cp;
                        v0 += old.x; v1 += old.y;
                    }
                    *cp = make_float2(v0, v1);
                }
            }
        }
    }
}

// ---------------- small fp32 GEMM (encoder K=16) ----------------
template <int K, int MOUT, bool RELU>
__global__ void __launch_bounds__(256) gemm_small(const float* __restrict__ A,
                                                  const float* __restrict__ W,
                                                  const float* __restrict__ bias,
                                                  float* __restrict__ C, int n) {
    constexpr int BM = 64, BK = 16, TM = 8, TN = 4;
    __shared__ float As[BK][BM + 4];
    __shared__ float Ws[BK][MOUT];
    int row0 = blockIdx.x * BM;
    int tid = threadIdx.x;
    int tx = tid & 31, ty = tid >> 5;
    float acc[TM][TN];
#pragma unroll
    for (int i = 0; i < TM; i++)
#pragma unroll
        for (int j = 0; j < TN; j++) acc[i][j] = 0.f;
    int a_row = tid >> 2, a_kq = (tid & 3) * 4;
    for (int k0 = 0; k0 < K; k0 += BK) {
        float4 av = make_float4(0.f, 0.f, 0.f, 0.f);
        int grow = row0 + a_row;
        if (grow < n) av = *(const float4*)(A + (size_t)grow * K + k0 + a_kq);
        As[a_kq + 0][a_row] = av.x;
        As[a_kq + 1][a_row] = av.y;
        As[a_kq + 2][a_row] = av.z;
        As[a_kq + 3][a_row] = av.w;
#pragma unroll
        for (int i = 0; i < BK * MOUT / (256 * 4); i++) {
            int lin = tid + i * 256;
            int wk = lin / (MOUT / 4);
            int wc = (lin % (MOUT / 4)) * 4;
            *(float4*)&Ws[wk][wc] = *(const float4*)(W + (size_t)(k0 + wk) * MOUT + wc);
        }
        __syncthreads();
#pragma unroll
        for (int kk = 0; kk < BK; kk++) {
            float a[TM], w[TN];
            *(float4*)&a[0] = *(float4*)&As[kk][ty * TM];
            *(float4*)&a[4] = *(float4*)&As[kk][ty * TM + 4];
            *(float4*)&w[0] = *(float4*)&Ws[kk][tx * TN];
#pragma unroll
            for (int i = 0; i < TM; i++)
#pragma unroll
                for (int j = 0; j < TN; j++) acc[i][j] += a[i] * w[j];
        }
        __syncthreads();
    }
#pragma unroll
    for (int i = 0; i < TM; i++) {
        int row = row0 + ty * TM + i;
        if (row < n) {
            float4 o;
            o.x = acc[i][0] + bias[tx * TN + 0];
            o.y = acc[i][1] + bias[tx * TN + 1];
            o.z = acc[i][2] + bias[tx * TN + 2];
            o.w = acc[i][3] + bias[tx * TN + 3];
            if (RELU) {
                o.x = fmaxf(o.x, 0.f); o.y = fmaxf(o.y, 0.f);
                o.z = fmaxf(o.z, 0.f); o.w = fmaxf(o.w, 0.f);
            }
            *(float4*)(C + (size_t)row * MOUT + tx * TN) = o;
        }
    }
}

// ---------------- LayerNorm ----------------
__global__ void ln_kernel(const float* __restrict__ x, const float* __restrict__ s,
                          const float* __restrict__ b, float* __restrict__ out, int n) {
    int row = blockIdx.x * 8 + (threadIdx.x >> 5);
    if (row >= n) return;
    int lane = threadIdx.x & 31;
    float4 v = *(const float4*)(x + (size_t)row * DD + lane * 4);
    float sum = v.x + v.y + v.z + v.w;
    float sq = v.x * v.x + v.y * v.y + v.z * v.z + v.w * v.w;
#pragma unroll
    for (int off = 16; off; off >>= 1) {
        sum += __shfl_xor_sync(0xffffffffu, sum, off);
        sq += __shfl_xor_sync(0xffffffffu, sq, off);
    }
    float mu = sum * (1.f / 128.f);
    float var = sq * (1.f / 128.f) - mu * mu;
    float rstd = rsqrtf(var + 1e-5f);
    float4 sv = *(const float4*)(s + lane * 4);
    float4 bv = *(const float4*)(b + lane * 4);
    float4 o;
    o.x = (v.x - mu) * rstd * sv.x + bv.x;
    o.y = (v.y - mu) * rstd * sv.y + bv.y;
    o.z = (v.z - mu) * rstd * sv.z + bv.z;
    o.w = (v.w - mu) * rstd * sv.w + bv.w;
    *(float4*)(out + (size_t)row * DD + lane * 4) = o;
}

// ---------------- CSR build ----------------
__global__ void zero_cnt_kernel() {
    int i = blockIdx.x * blockDim.x + threadIdx.x;
    if (i < NN) g_cnt[i] = 0;
}
__global__ void hist_kernel(const int* __restrict__ receivers) {
    int e = blockIdx.x * blockDim.x + threadIdx.x;
    if (e < EE) atomicAdd(&g_cnt[receivers[e]], 1);
}
__global__ void scan_kernel() {
    __shared__ int warp_sums[32];
    __shared__ int s_carry;
    int lane = threadIdx.x & 31;
    int wid = threadIdx.x >> 5;
    if (threadIdx.x == 0) s_carry = 0;
    __syncthreads();
    for (int base = 0; base < NN; base += 1024) {
        int i = base + threadIdx.x;
        int v = (i < NN) ? g_cnt[i] : 0;
        int incl = v;
#pragma unroll
        for (int off = 1; off < 32; off <<= 1) {
            int t = __shfl_up_sync(0xffffffffu, incl, off);
            if (lane >= off) incl += t;
        }
        if (lane == 31) warp_sums[wid] = incl;
        __syncthreads();
        if (wid == 0) {
            int ws = warp_sums[lane];
            int wincl = ws;
#pragma unroll
            for (int off = 1; off < 32; off <<= 1) {
                int t = __shfl_up_sync(0xffffffffu, wincl, off);
                if (lane >= off) wincl += t;
            }
            warp_sums[lane] = wincl - ws;
        }
        __syncthreads();
        int total_incl = s_carry + warp_sums[wid] + incl;
        if (i < NN) {
            g_rowptr[i + 1] = total_incl;
            g_cur[i] = total_incl - v;
        }
        __syncthreads();
        if (threadIdx.x == 1023) s_carry = total_incl;
        __syncthreads();
    }
    if (threadIdx.x == 0) g_rowptr[0] = 0;
}
__global__ void scatter_kernel(const int* __restrict__ senders,
                               const int* __restrict__ receivers) {
    int e = blockIdx.x * blockDim.x + threadIdx.x;
    if (e >= EE) return;
    int pos = atomicAdd(&g_cur[receivers[e]], 1);
    g_csr_snd[pos] = senders[e];
}

// ---------------- fused sparse attention ----------------
__global__ void attn_kernel() {
    int w = (blockIdx.x * blockDim.x + threadIdx.x) >> 5;
    if (w >= NN * HH) return;
    int lane = threadIdx.x & 31;
    int node = w >> 2;
    int head = w & 3;
    int off = head * DHH + lane;

    float qv = g_q[(size_t)node * DD + off];
    int beg = g_rowptr[node], end = g_rowptr[node + 1];

    float m = -INFINITY, den = 0.f, acc = 0.f;
    for (int j = beg; j < end; j++) {
        int snd = g_csr_snd[j];
        float kv = g_k[(size_t)snd * DD + off];
        float d = qv * kv;
#pragma unroll
        for (int o = 16; o; o >>= 1) d += __shfl_xor_sync(0xffffffffu, d, o);
        float s = d * 0.17677669529663687f;
        float nm = fmaxf(m, s);
        float alpha = __expf(m - nm);
        float a = __expf(s - nm);
        den = den * alpha + a;
        acc = acc * alpha + a * g_v[(size_t)snd * DD + off];
        m = nm;
    }
    g_h[(size_t)node * DD + off] = acc / (den + 1e-9f);
}

// ---------------- decoder ----------------
__global__ void decode_kernel(const float* __restrict__ x, const float* __restrict__ w1,
                              const float* __restrict__ b1, const float* __restrict__ w2,
                              const float* __restrict__ b2, float* __restrict__ out, int n) {
    int row = blockIdx.x * 4 + (threadIdx.x >> 5);
    if (row >= n) return;
    int lane = threadIdx.x & 31;
    float4 xr = *(const float4*)(x + (size_t)row * DD + lane * 4);
    float t[3];
#pragma unroll
    for (int o = 0; o < 3; o++) {
        float p = xr.x * w1[(lane * 4 + 0) * 3 + o] + xr.y * w1[(lane * 4 + 1) * 3 + o] +
                  xr.z * w1[(lane * 4 + 2) * 3 + o] + xr.w * w1[(lane * 4 + 3) * 3 + o];
#pragma unroll
        for (int off = 16; off; off >>= 1) p += __shfl_down_sync(0xffffffffu, p, off);
        t[o] = p;
    }
    if (lane == 0) {
        float r0 = fmaxf(t[0] + b1[0], 0.f);
        float r1 = fmaxf(t[1] + b1[1], 0.f);
        float r2 = fmaxf(t[2] + b1[2], 0.f);
#pragma unroll
        for (int o2 = 0; o2 < 3; o2++)
            out[row * 3 + o2] = r0 * w2[0 * 3 + o2] + r1 * w2[1 * 3 + o2] + r2 * w2[2 * 3 + o2] + b2[o2];
    }
}

// ---------------- host ----------------
extern "C" void kernel_launch(void* const* d_in, const int* in_sizes, int n_in,
                              void* d_out, int out_size) {
    const float* features = (const float*)d_in[0];
    const int* senders = (const int*)d_in[1];
    const int* receivers = (const int*)d_in[2];
    const float* enc_w1 = (const float*)d_in[3];
    const float* enc_b1 = (const float*)d_in[4];
    const float* enc_w2 = (const float*)d_in[5];
    const float* enc_b2 = (const float*)d_in[6];
    const float* wq = (const float*)d_in[7];
    const float* wk = (const float*)d_in[8];
    const float* wv = (const float*)d_in[9];
    const float* wo = (const float*)d_in[10];
    const float* ln1_s = (const float*)d_in[11];
    const float* ln1_b = (const float*)d_in[12];
    const float* ffn_w1 = (const float*)d_in[13];
    const float* ffn_b1 = (const float*)d_in[14];
    const float* ffn_w2 = (const float*)d_in[15];
    const float* ffn_b2 = (const float*)d_in[16];
    const float* ln2_s = (const float*)d_in[17];
    const float* ln2_b = (const float*)d_in[18];
    const float* dec_w1 = (const float*)d_in[19];
    const float* dec_b1 = (const float*)d_in[20];
    const float* dec_w2 = (const float*)d_in[21];
    const float* dec_b2 = (const float*)d_in[22];
    float* out = (float*)d_out;

    float* x;   cudaGetSymbolAddress((void**)&x, g_x);
    float* h;   cudaGetSymbolAddress((void**)&h, g_h);
    float* q;   cudaGetSymbolAddress((void**)&q, g_q);
    float* k;   cudaGetSymbolAddress((void**)&k, g_k);
    float* v;   cudaGetSymbolAddress((void**)&v, g_v);
    float* ffn; cudaGetSymbolAddress((void**)&ffn, g_ffn);

    const int MT = (NN + 127) / 128;  // 391
    dim3 t128(MT, 1), t512(MT, 4);

    // CSR build
    zero_cnt_kernel<<<(NN + 255) / 256, 256>>>();
    hist_kernel<<<(EE + 255) / 256, 256>>>(receivers);
    scan_kernel<<<1, 1024>>>();
    scatter_kernel<<<(EE + 255) / 256, 256>>>(senders, receivers);

    // encode
    gemm_small<D_IN, DD, true><<<(NN + 63) / 64, 256>>>(features, enc_w1, enc_b1, h, NN);
    gemm_mma<DD, DD, false, false><<<t128, 256>>>(h, enc_w2, enc_b2, x, NN);

    for (int l = 0; l < LL; l++) {
        const float* wq_l = wq + (size_t)l * DD * DD;
        const float* wk_l = wk + (size_t)l * DD * DD;
        const float* wv_l = wv + (size_t)l * DD * DD;
        const float* wo_l = wo + (size_t)l * DD * DD;

        ln_kernel<<<(NN + 7) / 8, 256>>>(x, ln1_s + l * DD, ln1_b + l * DD, h, NN);
        gemm_mma<DD, DD, false, false><<<t128, 256>>>(h, wq_l, nullptr, q, NN);
        gemm_mma<DD, DD, false, false><<<t128, 256>>>(h, wk_l, nullptr, k, NN);
        gemm_mma<DD, DD, false, false><<<t128, 256>>>(h, wv_l, nullptr, v, NN);
        attn_kernel<<<(NN * HH + 7) / 8, 256>>>();
        gemm_mma<DD, DD, false, true><<<t128, 256>>>(h, wo_l, nullptr, x, NN);

        ln_kernel<<<(NN + 7) / 8, 256>>>(x, ln2_s + l * DD, ln2_b + l * DD, h, NN);
        gemm_mma<DD, DFF, true, false><<<t512, 256>>>(h, ffn_w1 + (size_t)l * DD * DFF,
                                                      ffn_b1 + l * DFF, ffn, NN);
        gemm_mma<DFF, DD, false, true><<<t128, 256>>>(ffn, ffn_w2 + (size_t)l * DFF * DD,
                                                      ffn_b2 + l * DD, x, NN);
    }

    decode_kernel<<<(NN + 3) / 4, 128>>>(x, dec_w1, dec_b1, dec_w2, dec_b2, out, NN);
}

// round 5
// speedup vs baseline: 2.5798x; 1.1326x over previous
#include <cuda_runtime.h>
#include <cuda_bf16.h>
#include <cstdint>
#include <math.h>

#define NN 50000
#define EE 600000
#define D_IN 16
#define DD 128
#define HH 4
#define DHH 32
#define LL 4
#define DFF 512
#define D_OUT 3

// ---------------- scratch ----------------
__device__ float g_x[NN * DD];
__device__ float g_q[NN * DD];
__device__ float g_k[NN * DD];
__device__ float g_v[NN * DD];
__device__ __nv_bfloat16 g_hhi[NN * DD], g_hlo[NN * DD];       // split activations (128-wide)
__device__ __nv_bfloat16 g_mhi[NN * DFF], g_mlo[NN * DFF];     // split FFN mid (512-wide)
__device__ int g_cnt[NN];
__device__ int g_cur[NN];
__device__ int g_rowptr[NN + 1];
__device__ int g_csr_snd[EE];

// split transposed weights: Wt[col][k] bf16 hi/lo
__device__ __nv_bfloat16 wb_enc_hi[DD * DD], wb_enc_lo[DD * DD];
__device__ __nv_bfloat16 wb_q_hi[LL * DD * DD], wb_q_lo[LL * DD * DD];
__device__ __nv_bfloat16 wb_k_hi[LL * DD * DD], wb_k_lo[LL * DD * DD];
__device__ __nv_bfloat16 wb_v_hi[LL * DD * DD], wb_v_lo[LL * DD * DD];
__device__ __nv_bfloat16 wb_o_hi[LL * DD * DD], wb_o_lo[LL * DD * DD];
__device__ __nv_bfloat16 wb_f1_hi[LL * DD * DFF], wb_f1_lo[LL * DD * DFF];
__device__ __nv_bfloat16 wb_f2_hi[LL * DFF * DD], wb_f2_lo[LL * DFF * DD];

// ---------------- helpers ----------------
__device__ __forceinline__ void hmma_bf16(float* c, const uint32_t* a, uint32_t b0, uint32_t b1) {
    asm volatile(
        "mma.sync.aligned.m16n8k16.row.col.f32.bf16.bf16.f32 "
        "{%0,%1,%2,%3}, {%4,%5,%6,%7}, {%8,%9}, {%0,%1,%2,%3};"
        : "+f"(c[0]), "+f"(c[1]), "+f"(c[2]), "+f"(c[3])
        : "r"(a[0]), "r"(a[1]), "r"(a[2]), "r"(a[3]), "r"(b0), "r"(b1));
}
__device__ __forceinline__ void split2(float x, float y, uint32_t& hi, uint32_t& lo) {
    __nv_bfloat16 hx = __float2bfloat16(x);
    __nv_bfloat16 hy = __float2bfloat16(y);
    __nv_bfloat16 lx = __float2bfloat16(x - __bfloat162float(hx));
    __nv_bfloat16 ly = __float2bfloat16(y - __bfloat162float(hy));
    __nv_bfloat162 hp = __halves2bfloat162(hx, hy);
    __nv_bfloat162 lp = __halves2bfloat162(lx, ly);
    hi = *(uint32_t*)&hp;
    lo = *(uint32_t*)&lp;
}

// ---------------- weight split + transpose: W[K][M] -> Wt[M][K] hi/lo ----------------
// total = nmat*K*M elements, per-matrix transpose.
__global__ void split_w_kernel(const float* __restrict__ W, __nv_bfloat16* __restrict__ hi,
                               __nv_bfloat16* __restrict__ lo, int K, int M, int total) {
    int idx = blockIdx.x * blockDim.x + threadIdx.x;
    if (idx >= total) return;
    int km = K * M;
    int mat = idx / km;
    int rem = idx - mat * km;
    int r = rem / M, c = rem - r * M;
    float w = W[idx];
    __nv_bfloat16 h = __float2bfloat16(w);
    __nv_bfloat16 l = __float2bfloat16(w - __bfloat162float(h));
    int dst = mat * km + c * K + r;
    hi[dst] = h;
    lo[dst] = l;
}

// ---------------- HMMA bf16x3 GEMM on pre-split operands ----------------
// out[n,MOUT] = act(A[n,K] @ Wt^T + bias) (+C) ; A,Wt given as bf16 hi/lo planes.
// Block tile 128x128, BK=32, 256 threads = 8 warps (4m x 2n), warp tile 32x64.
template <int K, int MOUT, bool RELU, bool ADD, bool OSPLIT>
__global__ void __launch_bounds__(256) gemm_bf16(const __nv_bfloat16* __restrict__ Ahi,
                                                 const __nv_bfloat16* __restrict__ Alo,
                                                 const __nv_bfloat16* __restrict__ Bhi,
                                                 const __nv_bfloat16* __restrict__ Blo,
                                                 const float* __restrict__ bias,
                                                 float* __restrict__ C,
                                                 __nv_bfloat16* __restrict__ Ohi,
                                                 __nv_bfloat16* __restrict__ Olo, int n) {
    constexpr int STR = 20;
    __shared__ uint32_t sAhi[128][STR];
    __shared__ uint32_t sAlo[128][STR];
    __shared__ uint32_t sBhi[128][STR];
    __shared__ uint32_t sBlo[128][STR];

    int tid = threadIdx.x;
    int l = tid & 31;
    int wm = (tid >> 5) & 3;
    int wn = tid >> 7;
    int row0 = blockIdx.x * 128, col0 = blockIdx.y * 128;

    float acc[2][8][4];
#pragma unroll
    for (int a = 0; a < 2; a++)
#pragma unroll
        for (int b = 0; b < 8; b++)
#pragma unroll
            for (int c = 0; c < 4; c++) acc[a][b][c] = 0.f;

    const int ar = tid >> 1;   // staging row (A row / B out-col)
    const int kh = tid & 1;    // k half (16 values = 8 words = 32B)

    for (int k0 = 0; k0 < K; k0 += 32) {
        __syncthreads();
        {
            int grow = row0 + ar;
            if (grow < n) {
                const uint4* ah = (const uint4*)(Ahi + (size_t)grow * K + k0 + kh * 16);
                const uint4* al = (const uint4*)(Alo + (size_t)grow * K + k0 + kh * 16);
                uint4 h0 = ah[0], h1 = ah[1], l0 = al[0], l1 = al[1];
                *(uint4*)&sAhi[ar][kh * 8] = h0;
                *(uint4*)&sAhi[ar][kh * 8 + 4] = h1;
                *(uint4*)&sAlo[ar][kh * 8] = l0;
                *(uint4*)&sAlo[ar][kh * 8 + 4] = l1;
            } else {
                uint4 z = make_uint4(0, 0, 0, 0);
                *(uint4*)&sAhi[ar][kh * 8] = z;
                *(uint4*)&sAhi[ar][kh * 8 + 4] = z;
                *(uint4*)&sAlo[ar][kh * 8] = z;
                *(uint4*)&sAlo[ar][kh * 8 + 4] = z;
            }
            const uint4* bh = (const uint4*)(Bhi + (size_t)(col0 + ar) * K + k0 + kh * 16);
            const uint4* bl = (const uint4*)(Blo + (size_t)(col0 + ar) * K + k0 + kh * 16);
            uint4 h0 = bh[0], h1 = bh[1], l0 = bl[0], l1 = bl[1];
            *(uint4*)&sBhi[ar][kh * 8] = h0;
            *(uint4*)&sBhi[ar][kh * 8 + 4] = h1;
            *(uint4*)&sBlo[ar][kh * 8] = l0;
            *(uint4*)&sBlo[ar][kh * 8 + 4] = l1;
        }
        __syncthreads();

#pragma unroll
        for (int ks = 0; ks < 2; ks++) {
            int w = 8 * ks + (l & 3);
            uint32_t ah[2][4], al[2][4];
#pragma unroll
            for (int tm = 0; tm < 2; tm++) {
                int r0 = wm * 32 + tm * 16 + (l >> 2);
                ah[tm][0] = sAhi[r0][w];
                ah[tm][1] = sAhi[r0 + 8][w];
                ah[tm][2] = sAhi[r0][w + 4];
                ah[tm][3] = sAhi[r0 + 8][w + 4];
                al[tm][0] = sAlo[r0][w];
                al[tm][1] = sAlo[r0 + 8][w];
                al[tm][2] = sAlo[r0][w + 4];
                al[tm][3] = sAlo[r0 + 8][w + 4];
            }
#pragma unroll
            for (int tn = 0; tn < 8; tn++) {
                int nn = wn * 64 + tn * 8 + (l >> 2);
                uint32_t bh0 = sBhi[nn][w], bh1 = sBhi[nn][w + 4];
                uint32_t bl0 = sBlo[nn][w], bl1 = sBlo[nn][w + 4];
#pragma unroll
                for (int tm = 0; tm < 2; tm++) {
                    hmma_bf16(acc[tm][tn], ah[tm], bh0, bh1);
                    hmma_bf16(acc[tm][tn], ah[tm], bl0, bl1);
                    hmma_bf16(acc[tm][tn], al[tm], bh0, bh1);
                }
            }
        }
    }

#pragma unroll
    for (int tm = 0; tm < 2; tm++) {
#pragma unroll
        for (int tn = 0; tn < 8; tn++) {
            int row = row0 + wm * 32 + tm * 16 + (l >> 2);
            int col = col0 + wn * 64 + tn * 8 + (l & 3) * 2;
            float b0 = 0.f, b1 = 0.f;
            if (bias) { b0 = bias[col]; b1 = bias[col + 1]; }
#pragma unroll
            for (int half = 0; half < 2; half++) {
                int r = row + half * 8;
                if (r < n) {
                    float v0 = acc[tm][tn][half * 2 + 0] + b0;
                    float v1 = acc[tm][tn][half * 2 + 1] + b1;
                    if (RELU) { v0 = fmaxf(v0, 0.f); v1 = fmaxf(v1, 0.f); }
                    if (OSPLIT) {
                        uint32_t hi, lo;
                        split2(v0, v1, hi, lo);
                        *(uint32_t*)(Ohi + (size_t)r * MOUT + col) = hi;
                        *(uint32_t*)(Olo + (size_t)r * MOUT + col) = lo;
                    } else {
                        float2* cp = (float2*)(C + (size_t)r * MOUT + col);
                        if (ADD) {
                            float2 old = *cp;
                            v0 += old.x; v1 += old.y;
                        }
                        *cp = make_float2(v0, v1);
                    }
                }
            }
        }
    }
}

// ---------------- small fp32 GEMM (encoder K=16) -> split bf16 out ----------------
__global__ void __launch_bounds__(256) gemm_small(const float* __restrict__ A,
                                                  const float* __restrict__ W,
                                                  const float* __restrict__ bias,
                                                  __nv_bfloat16* __restrict__ Ohi,
                                                  __nv_bfloat16* __restrict__ Olo, int n) {
    constexpr int K = D_IN, MOUT = DD, BM = 64, BK = 16, TM = 8, TN = 4;
    __shared__ float As[BK][BM + 4];
    __shared__ float Ws[BK][MOUT];
    int row0 = blockIdx.x * BM;
    int tid = threadIdx.x;
    int tx = tid & 31, ty = tid >> 5;
    float acc[TM][TN];
#pragma unroll
    for (int i = 0; i < TM; i++)
#pragma unroll
        for (int j = 0; j < TN; j++) acc[i][j] = 0.f;
    int a_row = tid >> 2, a_kq = (tid & 3) * 4;
    {
        float4 av = make_float4(0.f, 0.f, 0.f, 0.f);
        int grow = row0 + a_row;
        if (grow < n) av = *(const float4*)(A + (size_t)grow * K + a_kq);
        As[a_kq + 0][a_row] = av.x;
        As[a_kq + 1][a_row] = av.y;
        As[a_kq + 2][a_row] = av.z;
        As[a_kq + 3][a_row] = av.w;
#pragma unroll
        for (int i = 0; i < 2; i++) {
            int lin = tid + i * 256;
            int wk = lin >> 5;
            int wc = (lin & 31) * 4;
            *(float4*)&Ws[wk][wc] = *(const float4*)(W + (size_t)wk * MOUT + wc);
        }
        __syncthreads();
#pragma unroll
        for (int kk = 0; kk < BK; kk++) {
            float a[TM], w[TN];
            *(float4*)&a[0] = *(float4*)&As[kk][ty * TM];
            *(float4*)&a[4] = *(float4*)&As[kk][ty * TM + 4];
            *(float4*)&w[0] = *(float4*)&Ws[kk][tx * TN];
#pragma unroll
            for (int i = 0; i < TM; i++)
#pragma unroll
                for (int j = 0; j < TN; j++) acc[i][j] += a[i] * w[j];
        }
    }
#pragma unroll
    for (int i = 0; i < TM; i++) {
        int row = row0 + ty * TM + i;
        if (row < n) {
            float v0 = fmaxf(acc[i][0] + bias[tx * TN + 0], 0.f);
            float v1 = fmaxf(acc[i][1] + bias[tx * TN + 1], 0.f);
            float v2 = fmaxf(acc[i][2] + bias[tx * TN + 2], 0.f);
            float v3 = fmaxf(acc[i][3] + bias[tx * TN + 3], 0.f);
            uint32_t h0, l0, h1, l1;
            split2(v0, v1, h0, l0);
            split2(v2, v3, h1, l1);
            *(uint2*)(Ohi + (size_t)row * MOUT + tx * TN) = make_uint2(h0, h1);
            *(uint2*)(Olo + (size_t)row * MOUT + tx * TN) = make_uint2(l0, l1);
        }
    }
}

// ---------------- LayerNorm -> split bf16 out ----------------
__global__ void ln_kernel(const float* __restrict__ x, const float* __restrict__ s,
                          const float* __restrict__ b, __nv_bfloat16* __restrict__ Ohi,
                          __nv_bfloat16* __restrict__ Olo, int n) {
    int row = blockIdx.x * 8 + (threadIdx.x >> 5);
    if (row >= n) return;
    int lane = threadIdx.x & 31;
    float4 v = *(const float4*)(x + (size_t)row * DD + lane * 4);
    float sum = v.x + v.y + v.z + v.w;
    float sq = v.x * v.x + v.y * v.y + v.z * v.z + v.w * v.w;
#pragma unroll
    for (int off = 16; off; off >>= 1) {
        sum += __shfl_xor_sync(0xffffffffu, sum, off);
        sq += __shfl_xor_sync(0xffffffffu, sq, off);
    }
    float mu = sum * (1.f / 128.f);
    float var = sq * (1.f / 128.f) - mu * mu;
    float rstd = rsqrtf(var + 1e-5f);
    float4 sv = *(const float4*)(s + lane * 4);
    float4 bv = *(const float4*)(b + lane * 4);
    float o0 = (v.x - mu) * rstd * sv.x + bv.x;
    float o1 = (v.y - mu) * rstd * sv.y + bv.y;
    float o2 = (v.z - mu) * rstd * sv.z + bv.z;
    float o3 = (v.w - mu) * rstd * sv.w + bv.w;
    uint32_t h0, l0, h1, l1;
    split2(o0, o1, h0, l0);
    split2(o2, o3, h1, l1);
    *(uint2*)(Ohi + (size_t)row * DD + lane * 4) = make_uint2(h0, h1);
    *(uint2*)(Olo + (size_t)row * DD + lane * 4) = make_uint2(l0, l1);
}

// ---------------- CSR build ----------------
__global__ void zero_cnt_kernel() {
    int i = blockIdx.x * blockDim.x + threadIdx.x;
    if (i < NN) g_cnt[i] = 0;
}
__global__ void hist_kernel(const int* __restrict__ receivers) {
    int e = blockIdx.x * blockDim.x + threadIdx.x;
    if (e < EE) atomicAdd(&g_cnt[receivers[e]], 1);
}
__global__ void scan_kernel() {
    __shared__ int warp_sums[32];
    __shared__ int s_carry;
    int lane = threadIdx.x & 31;
    int wid = threadIdx.x >> 5;
    if (threadIdx.x == 0) s_carry = 0;
    __syncthreads();
    for (int base = 0; base < NN; base += 1024) {
        int i = base + threadIdx.x;
        int v = (i < NN) ? g_cnt[i] : 0;
        int incl = v;
#pragma unroll
        for (int off = 1; off < 32; off <<= 1) {
            int t = __shfl_up_sync(0xffffffffu, incl, off);
            if (lane >= off) incl += t;
        }
        if (lane == 31) warp_sums[wid] = incl;
        __syncthreads();
        if (wid == 0) {
            int ws = warp_sums[lane];
            int wincl = ws;
#pragma unroll
            for (int off = 1; off < 32; off <<= 1) {
                int t = __shfl_up_sync(0xffffffffu, wincl, off);
                if (lane >= off) wincl += t;
            }
            warp_sums[lane] = wincl - ws;
        }
        __syncthreads();
        int total_incl = s_carry + warp_sums[wid] + incl;
        if (i < NN) {
            g_rowptr[i + 1] = total_incl;
            g_cur[i] = total_incl - v;
        }
        __syncthreads();
        if (threadIdx.x == 1023) s_carry = total_incl;
        __syncthreads();
    }
    if (threadIdx.x == 0) g_rowptr[0] = 0;
}
__global__ void scatter_kernel(const int* __restrict__ senders,
                               const int* __restrict__ receivers) {
    int e = blockIdx.x * blockDim.x + threadIdx.x;
    if (e >= EE) return;
    int pos = atomicAdd(&g_cur[receivers[e]], 1);
    g_csr_snd[pos] = senders[e];
}

// ---------------- fused sparse attention: warp per node, 4 heads in-warp ----------------
__global__ void attn_kernel() {
    int warp = (blockIdx.x * blockDim.x + threadIdx.x) >> 5;
    if (warp >= NN) return;
    int lane = threadIdx.x & 31;
    int node = warp;

    float4 q4 = *(const float4*)(g_q + (size_t)node * DD + lane * 4);
    int beg = g_rowptr[node], end = g_rowptr[node + 1];

    float m = -INFINITY, den = 0.f;
    float4 acc = make_float4(0.f, 0.f, 0.f, 0.f);
    int snd = (beg < end) ? g_csr_snd[beg] : 0;
    for (int j = beg; j < end; j++) {
        int snd_next = (j + 1 < end) ? g_csr_snd[j + 1] : 0;
        float4 k4 = *(const float4*)(g_k + (size_t)snd * DD + lane * 4);
        float4 v4 = *(const float4*)(g_v + (size_t)snd * DD + lane * 4);
        float d = q4.x * k4.x + q4.y * k4.y + q4.z * k4.z + q4.w * k4.w;
        d += __shfl_xor_sync(0xffffffffu, d, 1);
        d += __shfl_xor_sync(0xffffffffu, d, 2);
        d += __shfl_xor_sync(0xffffffffu, d, 4);
        float s = d * 0.17677669529663687f;  // 1/sqrt(32)
        float nm = fmaxf(m, s);
        float alpha = __expf(m - nm);
        float a = __expf(s - nm);
        den = den * alpha + a;
        acc.x = acc.x * alpha + a * v4.x;
        acc.y = acc.y * alpha + a * v4.y;
        acc.z = acc.z * alpha + a * v4.z;
        acc.w = acc.w * alpha + a * v4.w;
        m = nm;
        snd = snd_next;
    }
    float inv = 1.f / (den + 1e-9f);
    uint32_t h0, l0, h1, l1;
    split2(acc.x * inv, acc.y * inv, h0, l0);
    split2(acc.z * inv, acc.w * inv, h1, l1);
    *(uint2*)(g_hhi + (size_t)node * DD + lane * 4) = make_uint2(h0, h1);
    *(uint2*)(g_hlo + (size_t)node * DD + lane * 4) = make_uint2(l0, l1);
}

// ---------------- decoder ----------------
__global__ void decode_kernel(const float* __restrict__ x, const float* __restrict__ w1,
                              const float* __restrict__ b1, const float* __restrict__ w2,
                              const float* __restrict__ b2, float* __restrict__ out, int n) {
    int row = blockIdx.x * 4 + (threadIdx.x >> 5);
    if (row >= n) return;
    int lane = threadIdx.x & 31;
    float4 xr = *(const float4*)(x + (size_t)row * DD + lane * 4);
    float t[3];
#pragma unroll
    for (int o = 0; o < 3; o++) {
        float p = xr.x * w1[(lane * 4 + 0) * 3 + o] + xr.y * w1[(lane * 4 + 1) * 3 + o] +
                  xr.z * w1[(lane * 4 + 2) * 3 + o] + xr.w * w1[(lane * 4 + 3) * 3 + o];
#pragma unroll
        for (int off = 16; off; off >>= 1) p += __shfl_down_sync(0xffffffffu, p, off);
        t[o] = p;
    }
    if (lane == 0) {
        float r0 = fmaxf(t[0] + b1[0], 0.f);
        float r1 = fmaxf(t[1] + b1[1], 0.f);
        float r2 = fmaxf(t[2] + b1[2], 0.f);
#pragma unroll
        for (int o2 = 0; o2 < 3; o2++)
            out[row * 3 + o2] = r0 * w2[0 * 3 + o2] + r1 * w2[1 * 3 + o2] + r2 * w2[2 * 3 + o2] + b2[o2];
    }
}

// ---------------- host ----------------
extern "C" void kernel_launch(void* const* d_in, const int* in_sizes, int n_in,
                              void* d_out, int out_size) {
    const float* features = (const float*)d_in[0];
    const int* senders = (const int*)d_in[1];
    const int* receivers = (const int*)d_in[2];
    const float* enc_w1 = (const float*)d_in[3];
    const float* enc_b1 = (const float*)d_in[4];
    const float* enc_w2 = (const float*)d_in[5];
    const float* enc_b2 = (const float*)d_in[6];
    const float* wq = (const float*)d_in[7];
    const float* wk = (const float*)d_in[8];
    const float* wv = (const float*)d_in[9];
    const float* wo = (const float*)d_in[10];
    const float* ln1_s = (const float*)d_in[11];
    const float* ln1_b = (const float*)d_in[12];
    const float* ffn_w1 = (const float*)d_in[13];
    const float* ffn_b1 = (const float*)d_in[14];
    const float* ffn_w2 = (const float*)d_in[15];
    const float* ffn_b2 = (const float*)d_in[16];
    const float* ln2_s = (const float*)d_in[17];
    const float* ln2_b = (const float*)d_in[18];
    const float* dec_w1 = (const float*)d_in[19];
    const float* dec_b1 = (const float*)d_in[20];
    const float* dec_w2 = (const float*)d_in[21];
    const float* dec_b2 = (const float*)d_in[22];
    float* out = (float*)d_out;

    float* x;  cudaGetSymbolAddress((void**)&x, g_x);
    float* q;  cudaGetSymbolAddress((void**)&q, g_q);
    float* k;  cudaGetSymbolAddress((void**)&k, g_k);
    float* v;  cudaGetSymbolAddress((void**)&v, g_v);
    __nv_bfloat16 *hhi, *hlo, *mhi, *mlo;
    cudaGetSymbolAddress((void**)&hhi, g_hhi);
    cudaGetSymbolAddress((void**)&hlo, g_hlo);
    cudaGetSymbolAddress((void**)&mhi, g_mhi);
    cudaGetSymbolAddress((void**)&mlo, g_mlo);
    __nv_bfloat16 *we_h, *we_l, *wq_h, *wq_l, *wk_h, *wk_l, *wv_h, *wv_l, *wo_h, *wo_l;
    __nv_bfloat16 *f1_h, *f1_l, *f2_h, *f2_l;
    cudaGetSymbolAddress((void**)&we_h, wb_enc_hi);
    cudaGetSymbolAddress((void**)&we_l, wb_enc_lo);
    cudaGetSymbolAddress((void**)&wq_h, wb_q_hi);
    cudaGetSymbolAddress((void**)&wq_l, wb_q_lo);
    cudaGetSymbolAddress((void**)&wk_h, wb_k_hi);
    cudaGetSymbolAddress((void**)&wk_l, wb_k_lo);
    cudaGetSymbolAddress((void**)&wv_h, wb_v_hi);
    cudaGetSymbolAddress((void**)&wv_l, wb_v_lo);
    cudaGetSymbolAddress((void**)&wo_h, wb_o_hi);
    cudaGetSymbolAddress((void**)&wo_l, wb_o_lo);
    cudaGetSymbolAddress((void**)&f1_h, wb_f1_hi);
    cudaGetSymbolAddress((void**)&f1_l, wb_f1_lo);
    cudaGetSymbolAddress((void**)&f2_h, wb_f2_hi);
    cudaGetSymbolAddress((void**)&f2_l, wb_f2_lo);

    // weight split (once per call)
    split_w_kernel<<<(DD * DD + 255) / 256, 256>>>(enc_w2, we_h, we_l, DD, DD, DD * DD);
    split_w_kernel<<<(LL * DD * DD + 255) / 256, 256>>>(wq, wq_h, wq_l, DD, DD, LL * DD * DD);
    split_w_kernel<<<(LL * DD * DD + 255) / 256, 256>>>(wk, wk_h, wk_l, DD, DD, LL * DD * DD);
    split_w_kernel<<<(LL * DD * DD + 255) / 256, 256>>>(wv, wv_h, wv_l, DD, DD, LL * DD * DD);
    split_w_kernel<<<(LL * DD * DD + 255) / 256, 256>>>(wo, wo_h, wo_l, DD, DD, LL * DD * DD);
    split_w_kernel<<<(LL * DD * DFF + 255) / 256, 256>>>(ffn_w1, f1_h, f1_l, DD, DFF, LL * DD * DFF);
    split_w_kernel<<<(LL * DFF * DD + 255) / 256, 256>>>(ffn_w2, f2_h, f2_l, DFF, DD, LL * DFF * DD);

    // CSR build
    zero_cnt_kernel<<<(NN + 255) / 256, 256>>>();
    hist_kernel<<<(EE + 255) / 256, 256>>>(receivers);
    scan_kernel<<<1, 1024>>>();
    scatter_kernel<<<(EE + 255) / 256, 256>>>(senders, receivers);

    const int MT = (NN + 127) / 128;  // 391
    dim3 t128(MT, 1), t512(MT, 4);

    // encode
    gemm_small<<<(NN + 63) / 64, 256>>>(features, enc_w1, enc_b1, hhi, hlo, NN);
    gemm_bf16<DD, DD, false, false, false><<<t128, 256>>>(hhi, hlo, we_h, we_l, enc_b2, x, nullptr, nullptr, NN);

    for (int l = 0; l < LL; l++) {
        size_t o128 = (size_t)l * DD * DD, o512 = (size_t)l * DD * DFF;

        ln_kernel<<<(NN + 7) / 8, 256>>>(x, ln1_s + l * DD, ln1_b + l * DD, hhi, hlo, NN);
        gemm_bf16<DD, DD, false, false, false><<<t128, 256>>>(hhi, hlo, wq_h + o128, wq_l + o128, nullptr, q, nullptr, nullptr, NN);
        gemm_bf16<DD, DD, false, false, false><<<t128, 256>>>(hhi, hlo, wk_h + o128, wk_l + o128, nullptr, k, nullptr, nullptr, NN);
        gemm_bf16<DD, DD, false, false, false><<<t128, 256>>>(hhi, hlo, wv_h + o128, wv_l + o128, nullptr, v, nullptr, nullptr, NN);
        attn_kernel<<<(NN + 7) / 8, 256>>>();
        gemm_bf16<DD, DD, false, true, false><<<t128, 256>>>(hhi, hlo, wo_h + o128, wo_l + o128, nullptr, x, nullptr, nullptr, NN);

        ln_kernel<<<(NN + 7) / 8, 256>>>(x, ln2_s + l * DD, ln2_b + l * DD, hhi, hlo, NN);
        gemm_bf16<DD, DFF, true, false, true><<<t512, 256>>>(hhi, hlo, f1_h + o512, f1_l + o512, ffn_b1 + l * DFF, nullptr, mhi, mlo, NN);
        gemm_bf16<DFF, DD, false, true, false><<<t128, 256>>>(mhi, mlo, f2_h + o512, f2_l + o512, ffn_b2 + l * DD, x, nullptr, nullptr, NN);
    }

    decode_kernel<<<(NN + 3) / 4, 128>>>(x, dec_w1, dec_b1, dec_w2, dec_b2, out, NN);
}

// round 6
// speedup vs baseline: 2.9406x; 1.1399x over previous
#include <cuda_runtime.h>
#include <cuda_bf16.h>
#include <cstdint>
#include <math.h>

#define NN 50000
#define EE 600000
#define D_IN 16
#define DD 128
#define HH 4
#define DHH 32
#define LL 4
#define DFF 512
#define D_OUT 3

// ---------------- scratch ----------------
__device__ float g_x[NN * DD];
__device__ float g_qkv[NN * 384];
__device__ __nv_bfloat16 g_hhi[NN * DD], g_hlo[NN * DD];
__device__ __nv_bfloat16 g_mhi[NN * DFF], g_mlo[NN * DFF];
__device__ int g_cnt[NN];
__device__ int g_cur[NN];
__device__ int g_rowptr[NN + 1];
__device__ int g_csr_snd[EE];

// split transposed weights: Wt[col][k] bf16 hi/lo
__device__ __nv_bfloat16 wb_enc_hi[DD * DD], wb_enc_lo[DD * DD];
__device__ __nv_bfloat16 wb_qkv_hi[LL * 384 * DD], wb_qkv_lo[LL * 384 * DD];
__device__ __nv_bfloat16 wb_o_hi[LL * DD * DD], wb_o_lo[LL * DD * DD];
__device__ __nv_bfloat16 wb_f1_hi[LL * DD * DFF], wb_f1_lo[LL * DD * DFF];
__device__ __nv_bfloat16 wb_f2_hi[LL * DFF * DD], wb_f2_lo[LL * DFF * DD];

// ---------------- helpers ----------------
__device__ __forceinline__ void hmma_bf16(float* c, const uint32_t* a, uint32_t b0, uint32_t b1) {
    asm volatile(
        "mma.sync.aligned.m16n8k16.row.col.f32.bf16.bf16.f32 "
        "{%0,%1,%2,%3}, {%4,%5,%6,%7}, {%8,%9}, {%0,%1,%2,%3};"
        : "+f"(c[0]), "+f"(c[1]), "+f"(c[2]), "+f"(c[3])
        : "r"(a[0]), "r"(a[1]), "r"(a[2]), "r"(a[3]), "r"(b0), "r"(b1));
}
__device__ __forceinline__ void split2(float x, float y, uint32_t& hi, uint32_t& lo) {
    __nv_bfloat16 hx = __float2bfloat16(x);
    __nv_bfloat16 hy = __float2bfloat16(y);
    __nv_bfloat16 lx = __float2bfloat16(x - __bfloat162float(hx));
    __nv_bfloat16 ly = __float2bfloat16(y - __bfloat162float(hy));
    __nv_bfloat162 hp = __halves2bfloat162(hx, hy);
    __nv_bfloat162 lp = __halves2bfloat162(lx, ly);
    hi = *(uint32_t*)&hp;
    lo = *(uint32_t*)&lp;
}
__device__ __forceinline__ uint32_t smem_u32(const void* p) {
    uint32_t a;
    asm("{ .reg .u64 t; cvta.to.shared.u64 t, %1; cvt.u32.u64 %0, t; }" : "=r"(a) : "l"(p));
    return a;
}
__device__ __forceinline__ void cp16(uint32_t dst, const void* src, int sz) {
    asm volatile("cp.async.ca.shared.global [%0], [%1], 16, %2;" :: "r"(dst), "l"(src), "r"(sz));
}

// ---------------- weight split + transpose: W[K][M] -> Wt[col_off+c][k] hi/lo ----------------
__global__ void split_w_kernel(const float* __restrict__ W, __nv_bfloat16* __restrict__ hi,
                               __nv_bfloat16* __restrict__ lo, int K, int M, int total,
                               int out_cols, int col_off) {
    int idx = blockIdx.x * blockDim.x + threadIdx.x;
    if (idx >= total) return;
    int km = K * M;
    int mat = idx / km;
    int rem = idx - mat * km;
    int r = rem / M, c = rem - r * M;
    float w = W[idx];
    __nv_bfloat16 h = __float2bfloat16(w);
    __nv_bfloat16 l = __float2bfloat16(w - __bfloat162float(h));
    int dst = mat * (out_cols * K) + (c + col_off) * K + r;
    hi[dst] = h;
    lo[dst] = l;
}

// ---------------- double-buffered cp.async HMMA bf16x3 GEMM ----------------
// out[n,MOUT] = act(A[n,K] @ Wt^T + bias) (+C) on pre-split bf16 hi/lo planes.
// Block tile 128x128, BK=32, 256 threads (8 warps, 4m x 2n), warp tile 32x64.
// Dynamic smem: 2 buffers x 4 planes x 128 rows x 20 words = 81920 B.
template <int K, int MOUT, bool RELU, bool ADD, bool OSPLIT>
__global__ void __launch_bounds__(256) gemm_db(const __nv_bfloat16* __restrict__ Ahi,
                                               const __nv_bfloat16* __restrict__ Alo,
                                               const __nv_bfloat16* __restrict__ Bhi,
                                               const __nv_bfloat16* __restrict__ Blo,
                                               const float* __restrict__ bias,
                                               float* __restrict__ C,
                                               __nv_bfloat16* __restrict__ Ohi,
                                               __nv_bfloat16* __restrict__ Olo, int n) {
    extern __shared__ uint32_t S[];  // [2][4][128][20]
    constexpr int NCH = K / 32;
    constexpr int PL = 2560;    // words per plane
    constexpr int BUF = 10240;  // words per buffer

    int tid = threadIdx.x;
    int l = tid & 31;
    int wm = (tid >> 5) & 3;
    int wn = tid >> 7;
    int row0 = blockIdx.x * 128, col0 = blockIdx.y * 128;
    uint32_t sbase = smem_u32(S);

    float acc[2][8][4];
#pragma unroll
    for (int a = 0; a < 2; a++)
#pragma unroll
        for (int b = 0; b < 8; b++)
#pragma unroll
            for (int c = 0; c < 4; c++) acc[a][b][c] = 0.f;

    // ---- stage one 32-K chunk into buffer b via cp.async (2048 x 16B chunks) ----
    auto stage = [&](int b, int k0) {
#pragma unroll
        for (int i = 0; i < 8; i++) {
            int plane = i >> 1;                 // 0:Ahi 1:Alo 2:Bhi 3:Blo
            int cc = (i & 1) * 256 + tid;       // 0..511 within plane
            int row = cc >> 2, part = cc & 3;
            uint32_t daddr = sbase + (uint32_t)(b * BUF + plane * PL + row * 20 + part * 4) * 4;
            if (plane < 2) {
                int grow = row0 + row;
                int ok = grow < n;
                const __nv_bfloat16* base = (plane == 0) ? Ahi : Alo;
                const void* src = base + (size_t)(ok ? grow : 0) * K + k0 + part * 8;
                cp16(daddr, src, ok ? 16 : 0);
            } else {
                const __nv_bfloat16* base = (plane == 2) ? Bhi : Blo;
                const void* src = base + (size_t)(col0 + row) * K + k0 + part * 8;
                cp16(daddr, src, 16);
            }
        }
    };

    stage(0, 0);
    asm volatile("cp.async.commit_group;");

    for (int ch = 0; ch < NCH; ch++) {
        if (ch + 1 < NCH) {
            stage((ch + 1) & 1, (ch + 1) * 32);
            asm volatile("cp.async.commit_group;");
            asm volatile("cp.async.wait_group 1;");
        } else {
            asm volatile("cp.async.wait_group 0;");
        }
        __syncthreads();

        const uint32_t* bAhi = S + (ch & 1) * BUF;
        const uint32_t* bAlo = bAhi + PL;
        const uint32_t* bBhi = bAlo + PL;
        const uint32_t* bBlo = bBhi + PL;

#pragma unroll
        for (int ks = 0; ks < 2; ks++) {
            int w = 8 * ks + (l & 3);
            uint32_t ah[2][4], al[2][4];
#pragma unroll
            for (int tm = 0; tm < 2; tm++) {
                int r0 = wm * 32 + tm * 16 + (l >> 2);
                ah[tm][0] = bAhi[r0 * 20 + w];
                ah[tm][1] = bAhi[(r0 + 8) * 20 + w];
                ah[tm][2] = bAhi[r0 * 20 + w + 4];
                ah[tm][3] = bAhi[(r0 + 8) * 20 + w + 4];
                al[tm][0] = bAlo[r0 * 20 + w];
                al[tm][1] = bAlo[(r0 + 8) * 20 + w];
                al[tm][2] = bAlo[r0 * 20 + w + 4];
                al[tm][3] = bAlo[(r0 + 8) * 20 + w + 4];
            }
#pragma unroll
            for (int tn = 0; tn < 8; tn++) {
                int nn = wn * 64 + tn * 8 + (l >> 2);
                uint32_t bh0 = bBhi[nn * 20 + w], bh1 = bBhi[nn * 20 + w + 4];
                uint32_t bl0 = bBlo[nn * 20 + w], bl1 = bBlo[nn * 20 + w + 4];
#pragma unroll
                for (int tm = 0; tm < 2; tm++) {
                    hmma_bf16(acc[tm][tn], ah[tm], bh0, bh1);
                    hmma_bf16(acc[tm][tn], ah[tm], bl0, bl1);
                    hmma_bf16(acc[tm][tn], al[tm], bh0, bh1);
                }
            }
        }
        __syncthreads();
    }

#pragma unroll
    for (int tm = 0; tm < 2; tm++) {
#pragma unroll
        for (int tn = 0; tn < 8; tn++) {
            int row = row0 + wm * 32 + tm * 16 + (l >> 2);
            int col = col0 + wn * 64 + tn * 8 + (l & 3) * 2;
            float b0 = 0.f, b1 = 0.f;
            if (bias) { b0 = bias[col]; b1 = bias[col + 1]; }
#pragma unroll
            for (int half = 0; half < 2; half++) {
                int r = row + half * 8;
                if (r < n) {
                    float v0 = acc[tm][tn][half * 2 + 0] + b0;
                    float v1 = acc[tm][tn][half * 2 + 1] + b1;
                    if (RELU) { v0 = fmaxf(v0, 0.f); v1 = fmaxf(v1, 0.f); }
                    if (OSPLIT) {
                        uint32_t hi, lo;
                        split2(v0, v1, hi, lo);
                        *(uint32_t*)(Ohi + (size_t)r * MOUT + col) = hi;
                        *(uint32_t*)(Olo + (size_t)r * MOUT + col) = lo;
                    } else {
                        float2* cp = (float2*)(C + (size_t)r * MOUT + col);
                        if (ADD) {
                            float2 old = *cp;
                            v0 += old.x; v1 += old.y;
                        }
                        *cp = make_float2(v0, v1);
                    }
                }
            }
        }
    }
}

// ---------------- small fp32 GEMM (encoder K=16) -> split bf16 out ----------------
__global__ void __launch_bounds__(256) gemm_small(const float* __restrict__ A,
                                                  const float* __restrict__ W,
                                                  const float* __restrict__ bias,
                                                  __nv_bfloat16* __restrict__ Ohi,
                                                  __nv_bfloat16* __restrict__ Olo, int n) {
    constexpr int K = D_IN, MOUT = DD, BM = 64, BK = 16, TM = 8, TN = 4;
    __shared__ float As[BK][BM + 4];
    __shared__ float Ws[BK][MOUT];
    int row0 = blockIdx.x * BM;
    int tid = threadIdx.x;
    int tx = tid & 31, ty = tid >> 5;
    float acc[TM][TN];
#pragma unroll
    for (int i = 0; i < TM; i++)
#pragma unroll
        for (int j = 0; j < TN; j++) acc[i][j] = 0.f;
    int a_row = tid >> 2, a_kq = (tid & 3) * 4;
    {
        float4 av = make_float4(0.f, 0.f, 0.f, 0.f);
        int grow = row0 + a_row;
        if (grow < n) av = *(const float4*)(A + (size_t)grow * K + a_kq);
        As[a_kq + 0][a_row] = av.x;
        As[a_kq + 1][a_row] = av.y;
        As[a_kq + 2][a_row] = av.z;
        As[a_kq + 3][a_row] = av.w;
#pragma unroll
        for (int i = 0; i < 2; i++) {
            int lin = tid + i * 256;
            int wk = lin >> 5;
            int wc = (lin & 31) * 4;
            *(float4*)&Ws[wk][wc] = *(const float4*)(W + (size_t)wk * MOUT + wc);
        }
        __syncthreads();
#pragma unroll
        for (int kk = 0; kk < BK; kk++) {
            float a[TM], w[TN];
            *(float4*)&a[0] = *(float4*)&As[kk][ty * TM];
            *(float4*)&a[4] = *(float4*)&As[kk][ty * TM + 4];
            *(float4*)&w[0] = *(float4*)&Ws[kk][tx * TN];
#pragma unroll
            for (int i = 0; i < TM; i++)
#pragma unroll
                for (int j = 0; j < TN; j++) acc[i][j] += a[i] * w[j];
        }
    }
#pragma unroll
    for (int i = 0; i < TM; i++) {
        int row = row0 + ty * TM + i;
        if (row < n) {
            float v0 = fmaxf(acc[i][0] + bias[tx * TN + 0], 0.f);
            float v1 = fmaxf(acc[i][1] + bias[tx * TN + 1], 0.f);
            float v2 = fmaxf(acc[i][2] + bias[tx * TN + 2], 0.f);
            float v3 = fmaxf(acc[i][3] + bias[tx * TN + 3], 0.f);
            uint32_t h0, l0, h1, l1;
            split2(v0, v1, h0, l0);
            split2(v2, v3, h1, l1);
            *(uint2*)(Ohi + (size_t)row * MOUT + tx * TN) = make_uint2(h0, h1);
            *(uint2*)(Olo + (size_t)row * MOUT + tx * TN) = make_uint2(l0, l1);
        }
    }
}

// ---------------- LayerNorm -> split bf16 out ----------------
__global__ void ln_kernel(const float* __restrict__ x, const float* __restrict__ s,
                          const float* __restrict__ b, __nv_bfloat16* __restrict__ Ohi,
                          __nv_bfloat16* __restrict__ Olo, int n) {
    int row = blockIdx.x * 8 + (threadIdx.x >> 5);
    if (row >= n) return;
    int lane = threadIdx.x & 31;
    float4 v = *(const float4*)(x + (size_t)row * DD + lane * 4);
    float sum = v.x + v.y + v.z + v.w;
    float sq = v.x * v.x + v.y * v.y + v.z * v.z + v.w * v.w;
#pragma unroll
    for (int off = 16; off; off >>= 1) {
        sum += __shfl_xor_sync(0xffffffffu, sum, off);
        sq += __shfl_xor_sync(0xffffffffu, sq, off);
    }
    float mu = sum * (1.f / 128.f);
    float var = sq * (1.f / 128.f) - mu * mu;
    float rstd = rsqrtf(var + 1e-5f);
    float4 sv = *(const float4*)(s + lane * 4);
    float4 bv = *(const float4*)(b + lane * 4);
    float o0 = (v.x - mu) * rstd * sv.x + bv.x;
    float o1 = (v.y - mu) * rstd * sv.y + bv.y;
    float o2 = (v.z - mu) * rstd * sv.z + bv.z;
    float o3 = (v.w - mu) * rstd * sv.w + bv.w;
    uint32_t h0, l0, h1, l1;
    split2(o0, o1, h0, l0);
    split2(o2, o3, h1, l1);
    *(uint2*)(Ohi + (size_t)row * DD + lane * 4) = make_uint2(h0, h1);
    *(uint2*)(Olo + (size_t)row * DD + lane * 4) = make_uint2(l0, l1);
}

// ---------------- CSR build ----------------
__global__ void zero_cnt_kernel() {
    int i = blockIdx.x * blockDim.x + threadIdx.x;
    if (i < NN) g_cnt[i] = 0;
}
__global__ void hist_kernel(const int* __restrict__ receivers) {
    int e = blockIdx.x * blockDim.x + threadIdx.x;
    if (e < EE) atomicAdd(&g_cnt[receivers[e]], 1);
}
__global__ void scan_kernel() {
    __shared__ int warp_sums[32];
    __shared__ int s_carry;
    int lane = threadIdx.x & 31;
    int wid = threadIdx.x >> 5;
    if (threadIdx.x == 0) s_carry = 0;
    __syncthreads();
    for (int base = 0; base < NN; base += 1024) {
        int i = base + threadIdx.x;
        int v = (i < NN) ? g_cnt[i] : 0;
        int incl = v;
#pragma unroll
        for (int off = 1; off < 32; off <<= 1) {
            int t = __shfl_up_sync(0xffffffffu, incl, off);
            if (lane >= off) incl += t;
        }
        if (lane == 31) warp_sums[wid] = incl;
        __syncthreads();
        if (wid == 0) {
            int ws = warp_sums[lane];
            int wincl = ws;
#pragma unroll
            for (int off = 1; off < 32; off <<= 1) {
                int t = __shfl_up_sync(0xffffffffu, wincl, off);
                if (lane >= off) wincl += t;
            }
            warp_sums[lane] = wincl - ws;
        }
        __syncthreads();
        int total_incl = s_carry + warp_sums[wid] + incl;
        if (i < NN) {
            g_rowptr[i + 1] = total_incl;
            g_cur[i] = total_incl - v;
        }
        __syncthreads();
        if (threadIdx.x == 1023) s_carry = total_incl;
        __syncthreads();
    }
    if (threadIdx.x == 0) g_rowptr[0] = 0;
}
__global__ void scatter_kernel(const int* __restrict__ senders,
                               const int* __restrict__ receivers) {
    int e = blockIdx.x * blockDim.x + threadIdx.x;
    if (e >= EE) return;
    int pos = atomicAdd(&g_cur[receivers[e]], 1);
    g_csr_snd[pos] = senders[e];
}

// ---------------- fused sparse attention: warp per node, software-pipelined ----------------
__global__ void attn_kernel() {
    int warp = (blockIdx.x * blockDim.x + threadIdx.x) >> 5;
    if (warp >= NN) return;
    int lane = threadIdx.x & 31;
    int node = warp;
    int l4 = lane * 4;

    float4 q4 = *(const float4*)(g_qkv + (size_t)node * 384 + l4);
    int beg = g_rowptr[node], end = g_rowptr[node + 1];

    float m = -INFINITY, den = 0.f;
    float4 acc = make_float4(0.f, 0.f, 0.f, 0.f);

    if (beg < end) {
        int snd = g_csr_snd[beg];
        const float* kp = g_qkv + (size_t)snd * 384 + 128;
        float4 k4 = *(const float4*)(kp + l4);
        float4 v4 = *(const float4*)(kp + 128 + l4);
        for (int j = beg; j < end; j++) {
            int snd_n = (j + 1 < end) ? g_csr_snd[j + 1] : snd;
            const float* kpn = g_qkv + (size_t)snd_n * 384 + 128;
            float4 k4n = *(const float4*)(kpn + l4);
            float4 v4n = *(const float4*)(kpn + 128 + l4);

            float d = q4.x * k4.x + q4.y * k4.y + q4.z * k4.z + q4.w * k4.w;
            d += __shfl_xor_sync(0xffffffffu, d, 1);
            d += __shfl_xor_sync(0xffffffffu, d, 2);
            d += __shfl_xor_sync(0xffffffffu, d, 4);
            float s = d * 0.17677669529663687f;  // 1/sqrt(32)
            float nm = fmaxf(m, s);
            float alpha = __expf(m - nm);
            float a = __expf(s - nm);
            den = den * alpha + a;
            acc.x = acc.x * alpha + a * v4.x;
            acc.y = acc.y * alpha + a * v4.y;
            acc.z = acc.z * alpha + a * v4.z;
            acc.w = acc.w * alpha + a * v4.w;
            m = nm;
            k4 = k4n; v4 = v4n;
        }
    }
    float inv = 1.f / (den + 1e-9f);
    uint32_t h0, l0, h1, l1;
    split2(acc.x * inv, acc.y * inv, h0, l0);
    split2(acc.z * inv, acc.w * inv, h1, l1);
    *(uint2*)(g_hhi + (size_t)node * DD + l4) = make_uint2(h0, h1);
    *(uint2*)(g_hlo + (size_t)node * DD + l4) = make_uint2(l0, l1);
}

// ---------------- decoder ----------------
__global__ void decode_kernel(const float* __restrict__ x, const float* __restrict__ w1,
                              const float* __restrict__ b1, const float* __restrict__ w2,
                              const float* __restrict__ b2, float* __restrict__ out, int n) {
    int row = blockIdx.x * 4 + (threadIdx.x >> 5);
    if (row >= n) return;
    int lane = threadIdx.x & 31;
    float4 xr = *(const float4*)(x + (size_t)row * DD + lane * 4);
    float t[3];
#pragma unroll
    for (int o = 0; o < 3; o++) {
        float p = xr.x * w1[(lane * 4 + 0) * 3 + o] + xr.y * w1[(lane * 4 + 1) * 3 + o] +
                  xr.z * w1[(lane * 4 + 2) * 3 + o] + xr.w * w1[(lane * 4 + 3) * 3 + o];
#pragma unroll
        for (int off = 16; off; off >>= 1) p += __shfl_down_sync(0xffffffffu, p, off);
        t[o] = p;
    }
    if (lane == 0) {
        float r0 = fmaxf(t[0] + b1[0], 0.f);
        float r1 = fmaxf(t[1] + b1[1], 0.f);
        float r2 = fmaxf(t[2] + b1[2], 0.f);
#pragma unroll
        for (int o2 = 0; o2 < 3; o2++)
            out[row * 3 + o2] = r0 * w2[0 * 3 + o2] + r1 * w2[1 * 3 + o2] + r2 * w2[2 * 3 + o2] + b2[o2];
    }
}

// ---------------- host ----------------
extern "C" void kernel_launch(void* const* d_in, const int* in_sizes, int n_in,
                              void* d_out, int out_size) {
    const float* features = (const float*)d_in[0];
    const int* senders = (const int*)d_in[1];
    const int* receivers = (const int*)d_in[2];
    const float* enc_w1 = (const float*)d_in[3];
    const float* enc_b1 = (const float*)d_in[4];
    const float* enc_w2 = (const float*)d_in[5];
    const float* enc_b2 = (const float*)d_in[6];
    const float* wq = (const float*)d_in[7];
    const float* wk = (const float*)d_in[8];
    const float* wv = (const float*)d_in[9];
    const float* wo = (const float*)d_in[10];
    const float* ln1_s = (const float*)d_in[11];
    const float* ln1_b = (const float*)d_in[12];
    const float* ffn_w1 = (const float*)d_in[13];
    const float* ffn_b1 = (const float*)d_in[14];
    const float* ffn_w2 = (const float*)d_in[15];
    const float* ffn_b2 = (const float*)d_in[16];
    const float* ln2_s = (const float*)d_in[17];
    const float* ln2_b = (const float*)d_in[18];
    const float* dec_w1 = (const float*)d_in[19];
    const float* dec_b1 = (const float*)d_in[20];
    const float* dec_w2 = (const float*)d_in[21];
    const float* dec_b2 = (const float*)d_in[22];
    float* out = (float*)d_out;

    float* x;    cudaGetSymbolAddress((void**)&x, g_x);
    float* qkv;  cudaGetSymbolAddress((void**)&qkv, g_qkv);
    __nv_bfloat16 *hhi, *hlo, *mhi, *mlo;
    cudaGetSymbolAddress((void**)&hhi, g_hhi);
    cudaGetSymbolAddress((void**)&hlo, g_hlo);
    cudaGetSymbolAddress((void**)&mhi, g_mhi);
    cudaGetSymbolAddress((void**)&mlo, g_mlo);
    __nv_bfloat16 *we_h, *we_l, *wqkv_h, *wqkv_l, *wo_h, *wo_l, *f1_h, *f1_l, *f2_h, *f2_l;
    cudaGetSymbolAddress((void**)&we_h, wb_enc_hi);
    cudaGetSymbolAddress((void**)&we_l, wb_enc_lo);
    cudaGetSymbolAddress((void**)&wqkv_h, wb_qkv_hi);
    cudaGetSymbolAddress((void**)&wqkv_l, wb_qkv_lo);
    cudaGetSymbolAddress((void**)&wo_h, wb_o_hi);
    cudaGetSymbolAddress((void**)&wo_l, wb_o_lo);
    cudaGetSymbolAddress((void**)&f1_h, wb_f1_hi);
    cudaGetSymbolAddress((void**)&f1_l, wb_f1_lo);
    cudaGetSymbolAddress((void**)&f2_h, wb_f2_hi);
    cudaGetSymbolAddress((void**)&f2_l, wb_f2_lo);

    const int SMEM_DB = 2 * 4 * 128 * 20 * 4;  // 81920
    cudaFuncSetAttribute(gemm_db<DD, DD, false, false, false>, cudaFuncAttributeMaxDynamicSharedMemorySize, SMEM_DB);
    cudaFuncSetAttribute(gemm_db<DD, 384, false, false, false>, cudaFuncAttributeMaxDynamicSharedMemorySize, SMEM_DB);
    cudaFuncSetAttribute(gemm_db<DD, DD, false, true, false>, cudaFuncAttributeMaxDynamicSharedMemorySize, SMEM_DB);
    cudaFuncSetAttribute(gemm_db<DD, DFF, true, false, true>, cudaFuncAttributeMaxDynamicSharedMemorySize, SMEM_DB);
    cudaFuncSetAttribute(gemm_db<DFF, DD, false, true, false>, cudaFuncAttributeMaxDynamicSharedMemorySize, SMEM_DB);

    // weight split (once per call)
    split_w_kernel<<<(DD * DD + 255) / 256, 256>>>(enc_w2, we_h, we_l, DD, DD, DD * DD, DD, 0);
    split_w_kernel<<<(LL * DD * DD + 255) / 256, 256>>>(wq, wqkv_h, wqkv_l, DD, DD, LL * DD * DD, 384, 0);
    split_w_kernel<<<(LL * DD * DD + 255) / 256, 256>>>(wk, wqkv_h, wqkv_l, DD, DD, LL * DD * DD, 384, 128);
    split_w_kernel<<<(LL * DD * DD + 255) / 256, 256>>>(wv, wqkv_h, wqkv_l, DD, DD, LL * DD * DD, 384, 256);
    split_w_kernel<<<(LL * DD * DD + 255) / 256, 256>>>(wo, wo_h, wo_l, DD, DD, LL * DD * DD, DD, 0);
    split_w_kernel<<<(LL * DD * DFF + 255) / 256, 256>>>(ffn_w1, f1_h, f1_l, DD, DFF, LL * DD * DFF, DFF, 0);
    split_w_kernel<<<(LL * DFF * DD + 255) / 256, 256>>>(ffn_w2, f2_h, f2_l, DFF, DD, LL * DFF * DD, DD, 0);

    // CSR build
    zero_cnt_kernel<<<(NN + 255) / 256, 256>>>();
    hist_kernel<<<(EE + 255) / 256, 256>>>(receivers);
    scan_kernel<<<1, 1024>>>();
    scatter_kernel<<<(EE + 255) / 256, 256>>>(senders, receivers);

    const int MT = (NN + 127) / 128;  // 391
    dim3 t128(MT, 1), t384(MT, 3), t512(MT, 4);

    // encode
    gemm_small<<<(NN + 63) / 64, 256>>>(features, enc_w1, enc_b1, hhi, hlo, NN);
    gemm_db<DD, DD, false, false, false><<<t128, 256, SMEM_DB>>>(hhi, hlo, we_h, we_l, enc_b2, x, nullptr, nullptr, NN);

    for (int l = 0; l < LL; l++) {
        size_t o384 = (size_t)l * 384 * DD;
        size_t o128 = (size_t)l * DD * DD;
        size_t o512 = (size_t)l * DD * DFF;

        ln_kernel<<<(NN + 7) / 8, 256>>>(x, ln1_s + l * DD, ln1_b + l * DD, hhi, hlo, NN);
        gemm_db<DD, 384, false, false, false><<<t384, 256, SMEM_DB>>>(hhi, hlo, wqkv_h + o384, wqkv_l + o384, nullptr, qkv, nullptr, nullptr, NN);
        attn_kernel<<<(NN + 7) / 8, 256>>>();
        gemm_db<DD, DD, false, true, false><<<t128, 256, SMEM_DB>>>(hhi, hlo, wo_h + o128, wo_l + o128, nullptr, x, nullptr, nullptr, NN);

        ln_kernel<<<(NN + 7) / 8, 256>>>(x, ln2_s + l * DD, ln2_b + l * DD, hhi, hlo, NN);
        gemm_db<DD, DFF, true, false, true><<<t512, 256, SMEM_DB>>>(hhi, hlo, f1_h + o512, f1_l + o512, ffn_b1 + l * DFF, nullptr, mhi, mlo, NN);
        gemm_db<DFF, DD, false, true, false><<<t128, 256, SMEM_DB>>>(mhi, mlo, f2_h + o512, f2_l + o512, ffn_b2 + l * DD, x, nullptr, nullptr, NN);
    }

    decode_kernel<<<(NN + 3) / 4, 128>>>(x, dec_w1, dec_b1, dec_w2, dec_b2, out, NN);
}